// round 2
// baseline (speedup 1.0000x reference)
#include <cuda_runtime.h>
#include <cuda_bf16.h>
#include <cstdint>

// out[n,f] = (1/25) * sum_s relu( dot(E[nbr[n,s],:], W[f,:]) + b[f] )
// N_NODES=50000, S=25, D=128, TABLE=100000
//
// One node per 128-thread block. Gather 25 embedding rows (512B each) into
// smem, then each thread owns one output feature f and runs 25 packed-K
// dot products using fma.rn.f32x2 (even-k lane / odd-k lane partial sums).
//
// neighbors dtype is detected at runtime (int32 vs int64): JAX downcasts
// jnp.int64 to int32 unless x64 mode is on, so we must not assume.

#define S_SAMPLES 25
#define FDIM 128
#define TABLE_SIZE 100000

__device__ int g_idx_is64;

__global__ void detect_idx_dtype(const int* __restrict__ nb32) {
    // If data is int64 (little-endian), the hi word of every value <100000 is 0.
    // If data is int32, odd words are random indices; P(all 32 zero) ~ 0.
    int is64 = 1;
    #pragma unroll
    for (int i = 1; i < 64; i += 2) {
        if (nb32[i] != 0) { is64 = 0; }
    }
    g_idx_is64 = is64;
}

__device__ __forceinline__ void fma2(unsigned long long& d,
                                     unsigned long long a,
                                     unsigned long long b) {
    asm("fma.rn.f32x2 %0, %1, %2, %0;" : "+l"(d) : "l"(a), "l"(b));
}

__device__ __forceinline__ void unpack2(float& lo, float& hi, unsigned long long v) {
    asm("mov.b64 {%0, %1}, %2;" : "=f"(lo), "=f"(hi) : "l"(v));
}

__global__ __launch_bounds__(FDIM) void meanpool_kernel(
    const void* __restrict__ neighbors_raw,   // [N, 25] int32 OR int64
    const float* __restrict__ emb_table,      // [100000, 128]
    const float* __restrict__ W,              // [128, 128] row-major (f, d)
    const float* __restrict__ b,              // [128]
    float* __restrict__ out,                  // [N, 128]
    int n_nodes)
{
    __shared__ float4 sE4[S_SAMPLES * 32];   // 25 rows x 128 floats = 12.8 KB

    const int n = blockIdx.x;
    if (n >= n_nodes) return;

    const int tid  = threadIdx.x;
    const int warp = tid >> 5;
    const int lane = tid & 31;
    const int is64 = g_idx_is64;

    // ---- Phase 1: gather 25 embedding rows into smem (coalesced) ----
    const float4* __restrict__ table4 = reinterpret_cast<const float4*>(emb_table);
    const int* __restrict__       nb32 = (const int*)neighbors_raw;
    const long long* __restrict__ nb64 = (const long long*)neighbors_raw;

    for (int s = warp; s < S_SAMPLES; s += 4) {
        const long long e = (long long)n * S_SAMPLES + s;
        long long nb = is64 ? __ldg(&nb64[e]) : (long long)__ldg(&nb32[e]);
        // clamp: never IMA even if dtype detection is somehow wrong
        nb = nb < 0 ? 0 : (nb >= TABLE_SIZE ? TABLE_SIZE - 1 : nb);
        sE4[s * 32 + lane] = __ldg(&table4[nb * 32 + lane]);
    }
    __syncthreads();

    // ---- Phase 2: thread f computes 25 dot products, packed over K ----
    const int f = tid;
    unsigned long long acc[S_SAMPLES];
    #pragma unroll
    for (int s = 0; s < S_SAMPLES; ++s) acc[s] = 0ULL;

    // View smem rows and the W row as pairs-of-f32-pairs (16B = {b64, b64}).
    const ulonglong2* __restrict__ sEv  = reinterpret_cast<const ulonglong2*>(sE4);
    const ulonglong2* __restrict__ Wrow =
        reinterpret_cast<const ulonglong2*>(W) + (size_t)f * (FDIM / 4);

    #pragma unroll 1
    for (int k4 = 0; k4 < FDIM / 4; ++k4) {
        const ulonglong2 w = __ldg(&Wrow[k4]);   // W[f][4k..4k+3], L1-resident
        #pragma unroll
        for (int s = 0; s < S_SAMPLES; ++s) {
            const ulonglong2 e = sEv[s * 32 + k4];  // broadcast LDS.128
            fma2(acc[s], e.x, w.x);
            fma2(acc[s], e.y, w.y);
        }
    }

    // ---- Epilogue: lo+hi combine, bias, relu, mean ----
    const float bias = __ldg(&b[f]);
    float sum = 0.0f;
    #pragma unroll
    for (int s = 0; s < S_SAMPLES; ++s) {
        float lo, hi;
        unpack2(lo, hi, acc[s]);
        float h = (lo + hi) + bias;
        sum += fmaxf(h, 0.0f);
    }
    out[(size_t)n * FDIM + f] = sum * (1.0f / (float)S_SAMPLES);
}

extern "C" void kernel_launch(void* const* d_in, const int* in_sizes, int n_in,
                              void* d_out, int out_size) {
    const void*  neighbors = d_in[0];
    const float* emb_table = (const float*)d_in[1];
    const float* W         = (const float*)d_in[2];
    const float* b         = (const float*)d_in[3];
    float*       out       = (float*)d_out;

    const int n_nodes = in_sizes[0] / S_SAMPLES;

    detect_idx_dtype<<<1, 1>>>((const int*)neighbors);
    meanpool_kernel<<<n_nodes, FDIM>>>(neighbors, emb_table, W, b, out, n_nodes);
}

// round 3
// speedup vs baseline: 1.6656x; 1.6656x over previous
#include <cuda_runtime.h>
#include <cuda_bf16.h>
#include <cstdint>

// out[n,f] = (1/25) * sum_s relu( dot(E[nbr[n,s],:], W[f,:]) + b[f] )
// N=50000, S=25, D=F=128, TABLE=100000. neighbors dtype auto-detected (i32/i64).
//
// Persistent blocks: grid=148, 256 threads = 4 groups x 64. Each group handles
// one node per iteration. W is staged in smem ONCE per block, transposed to
// WP4[k4][f] so w-loads are conflict-free LDS.128. Each thread computes two
// output features (f, f+64) with k-packed fma.rn.f32x2 accumulators, so each
// broadcast e-load feeds 4 FFMA2.

#define S_SAMPLES 25
#define FDIM 128
#define TABLE_SIZE 100000
#define GROUPS 4
#define GROUP_THREADS 64
#define BLOCK_THREADS 256
#define GRID_BLOCKS 148

// smem: WP4 [32][128] float4 = 64KB, then E4 [4][25][32] float4 = 50KB
#define SMEM_W_BYTES (32 * 128 * 16)
#define SMEM_E_BYTES (GROUPS * S_SAMPLES * 32 * 16)
#define SMEM_TOTAL (SMEM_W_BYTES + SMEM_E_BYTES)

__device__ int g_idx_is64;

__global__ void detect_idx_dtype(const int* __restrict__ nb32) {
    // int64 little-endian: hi word of every value <100000 is 0.
    // int32: odd words are random indices; P(all zero) ~ 0.
    int is64 = 1;
    #pragma unroll
    for (int i = 1; i < 64; i += 2) {
        if (nb32[i] != 0) is64 = 0;
    }
    g_idx_is64 = is64;
}

__device__ __forceinline__ void fma2(unsigned long long& d,
                                     unsigned long long a,
                                     unsigned long long b) {
    asm("fma.rn.f32x2 %0, %1, %2, %0;" : "+l"(d) : "l"(a), "l"(b));
}

__device__ __forceinline__ void unpack2(float& lo, float& hi, unsigned long long v) {
    asm("mov.b64 {%0, %1}, %2;" : "=f"(lo), "=f"(hi) : "l"(v));
}

__global__ __launch_bounds__(BLOCK_THREADS, 1) void meanpool_kernel(
    const void* __restrict__ neighbors_raw,
    const float* __restrict__ emb_table,
    const float* __restrict__ W,     // [128][128] row-major (f, d)
    const float* __restrict__ b,
    float* __restrict__ out,
    int n_nodes)
{
    extern __shared__ char smem[];
    float4* __restrict__ WP4 = (float4*)smem;                  // [k4][f] = [32][128]
    float4* __restrict__ E4  = (float4*)(smem + SMEM_W_BYTES); // [g][s][k4] = [4][25][32]

    const int tid  = threadIdx.x;
    const int g    = tid >> 6;
    const int gtid = tid & 63;
    const int is64 = g_idx_is64;

    // ---- Stage W transposed: WP4[k4][f] = W[f][4k4..4k4+3] (coalesced reads) ----
    const float4* __restrict__ W4 = (const float4*)W;
    for (int i = tid; i < FDIM * 32; i += BLOCK_THREADS) {
        int f = i >> 5, k4 = i & 31;
        WP4[k4 * FDIM + f] = __ldg(&W4[f * 32 + k4]);
    }
    const float bias0 = __ldg(&b[gtid]);
    const float bias1 = __ldg(&b[gtid + 64]);
    __syncthreads();

    const int* __restrict__       nb32 = (const int*)neighbors_raw;
    const long long* __restrict__ nb64 = (const long long*)neighbors_raw;
    const float4* __restrict__ table4 = (const float4*)emb_table;

    const int stride = GRID_BLOCKS * GROUPS;   // 592 nodes per sweep
    const int niters = (n_nodes + stride - 1) / stride;

    for (int it = 0; it < niters; ++it) {
        const int n = it * stride + blockIdx.x * GROUPS + g;
        const bool active = (n < n_nodes);

        // ---- gather 25 rows for this group's node (coalesced 512B rows) ----
        if (active) {
            for (int i = gtid; i < S_SAMPLES * 32; i += GROUP_THREADS) {
                int s = i >> 5, c = i & 31;
                long long e = (long long)n * S_SAMPLES + s;
                long long nb = is64 ? __ldg(&nb64[e]) : (long long)__ldg(&nb32[e]);
                nb = nb < 0 ? 0 : (nb >= TABLE_SIZE ? TABLE_SIZE - 1 : nb);
                E4[(g * S_SAMPLES + s) * 32 + c] = __ldg(&table4[nb * 32 + c]);
            }
        }
        __syncthreads();

        if (active) {
            unsigned long long acc0[S_SAMPLES], acc1[S_SAMPLES];
            #pragma unroll
            for (int s = 0; s < S_SAMPLES; ++s) { acc0[s] = 0ULL; acc1[s] = 0ULL; }

            const ulonglong2* __restrict__ Ev =
                (const ulonglong2*)(E4 + g * S_SAMPLES * 32);  // [25][32]
            const ulonglong2* __restrict__ Wv = (const ulonglong2*)WP4;  // [32][128]

            #pragma unroll 1
            for (int k4 = 0; k4 < 32; ++k4) {
                const ulonglong2 w0 = Wv[k4 * FDIM + gtid];        // conflict-free LDS.128
                const ulonglong2 w1 = Wv[k4 * FDIM + gtid + 64];
                #pragma unroll
                for (int s = 0; s < S_SAMPLES; ++s) {
                    const ulonglong2 e = Ev[s * 32 + k4];          // broadcast LDS.128
                    fma2(acc0[s], e.x, w0.x);
                    fma2(acc0[s], e.y, w0.y);
                    fma2(acc1[s], e.x, w1.x);
                    fma2(acc1[s], e.y, w1.y);
                }
            }

            float sum0 = 0.0f, sum1 = 0.0f;
            #pragma unroll
            for (int s = 0; s < S_SAMPLES; ++s) {
                float lo, hi;
                unpack2(lo, hi, acc0[s]);
                sum0 += fmaxf(lo + hi + bias0, 0.0f);
                unpack2(lo, hi, acc1[s]);
                sum1 += fmaxf(lo + hi + bias1, 0.0f);
            }
            out[(size_t)n * FDIM + gtid]      = sum0 * (1.0f / S_SAMPLES);
            out[(size_t)n * FDIM + gtid + 64] = sum1 * (1.0f / S_SAMPLES);
        }
        __syncthreads();   // E tile reused next iteration
    }
}

extern "C" void kernel_launch(void* const* d_in, const int* in_sizes, int n_in,
                              void* d_out, int out_size) {
    const void*  neighbors = d_in[0];
    const float* emb_table = (const float*)d_in[1];
    const float* W         = (const float*)d_in[2];
    const float* b         = (const float*)d_in[3];
    float*       out       = (float*)d_out;

    const int n_nodes = in_sizes[0] / S_SAMPLES;

    cudaFuncSetAttribute(meanpool_kernel,
                         cudaFuncAttributeMaxDynamicSharedMemorySize, SMEM_TOTAL);

    detect_idx_dtype<<<1, 1>>>((const int*)neighbors);
    meanpool_kernel<<<GRID_BLOCKS, BLOCK_THREADS, SMEM_TOTAL>>>(
        neighbors, emb_table, W, b, out, n_nodes);
}

// round 5
// speedup vs baseline: 2.1073x; 1.2652x over previous
#include <cuda_runtime.h>
#include <cuda_bf16.h>
#include <cstdint>

// out[n,f] = (1/25) * sum_s relu( dot(E[nbr[n,s],:], W[f,:]) + b[f] )
// Warp-level mma.sync (HMMA, baseline PTX — tcgen05 is sm_103a-gated and the
// harness targets compute_103). bf16 3-split for fp32 precision:
//   D = Ehi@Whi^T + Ehi@Wlo^T + Elo@Whi^T  (fp32 accumulate)
// Persistent grid=148, 256 thr = 8 warps (4m x 2n), tile M=128(125 rows),
// N=128, K=128. W staged once per CTA. Fused bias+relu+meanpool epilogue.

#define S_SAMPLES 25
#define FDIM 128
#define TABLE_SIZE 100000
#define ROWS_PER_TILE 125
#define NODES_PER_TILE 5
#define BLOCK_THREADS 256
#define GRID_BLOCKS 148

// bf16 tiles: [128 rows][128 k] = 128 rows x 256B = 32KB each
#define E_HI_OFF 0
#define E_LO_OFF 32768
#define W_HI_OFF 65536
#define W_LO_OFF 98304
#define H_OFF    131072
#define H_STRIDE 129
#define B_OFF    (H_OFF + 128 * H_STRIDE * 4)   // 197120
#define SMEM_TOTAL (B_OFF + 512 + 16)

__device__ int g_idx_is64;

__global__ void detect_idx_dtype(const int* __restrict__ nb32) {
    // int64 LE: hi word of every value <100000 is 0; int32: odd words random.
    int is64 = 1;
    #pragma unroll
    for (int i = 1; i < 64; i += 2) if (nb32[i] != 0) is64 = 0;
    g_idx_is64 = is64;
}

// ---------------- helpers ----------------
__device__ __forceinline__ uint32_t smem_u32(const void* p) {
    uint32_t a;
    asm("{ .reg .u64 t; cvta.to.shared.u64 t, %1; cvt.u32.u64 %0, t; }" : "=r"(a) : "l"(p));
    return a;
}

// XOR swizzle: 256B rows of bf16[128]; 16B chunk index ^ (row&7) -> conflict-free
// for both 8-row ldmatrix phases and 8-row B-fragment loads.
__device__ __forceinline__ uint32_t swz(int row, int chunk) {
    return (uint32_t)row * 256u + (uint32_t)(((chunk ^ (row & 7)) & 15) * 16);
}

__device__ __forceinline__ void ldm_x4(uint32_t* a, uint32_t addr) {
    asm volatile("ldmatrix.sync.aligned.m8n8.x4.shared.b16 {%0,%1,%2,%3}, [%4];"
                 : "=r"(a[0]), "=r"(a[1]), "=r"(a[2]), "=r"(a[3]) : "r"(addr));
}

__device__ __forceinline__ void mma_bf16(float* d, const uint32_t* a,
                                         uint32_t b0, uint32_t b1) {
    asm volatile(
        "mma.sync.aligned.m16n8k16.row.col.f32.bf16.bf16.f32 "
        "{%0,%1,%2,%3}, {%4,%5,%6,%7}, {%8,%9}, {%0,%1,%2,%3};"
        : "+f"(d[0]), "+f"(d[1]), "+f"(d[2]), "+f"(d[3])
        : "r"(a[0]), "r"(a[1]), "r"(a[2]), "r"(a[3]), "r"(b0), "r"(b1));
}

__device__ __forceinline__ uint32_t pack_bf2(float a, float b) {
    uint32_t r;
    asm("{ .reg .b16 lo, hi; cvt.rn.bf16.f32 lo, %1; cvt.rn.bf16.f32 hi, %2;"
        " mov.b32 %0, {lo, hi}; }" : "=r"(r) : "f"(a), "f"(b));
    return r;
}
__device__ __forceinline__ float bf_trunc(float x) {
    uint32_t r;
    asm("{ .reg .b16 t; cvt.rn.bf16.f32 t, %1; mov.b32 %0, {t, 0}; }" : "=r"(r) : "f"(x));
    return __uint_as_float(r << 16);
}

// float4 (k = 4q..4q+3) -> hi/lo bf16x4 at swizzled smem
__device__ __forceinline__ void store_split(char* hiB, char* loB, int r, int q, float4 v) {
    float hx = bf_trunc(v.x), hy = bf_trunc(v.y), hz = bf_trunc(v.z), hw = bf_trunc(v.w);
    uint2 hi = make_uint2(pack_bf2(hx, hy), pack_bf2(hz, hw));
    uint2 lo = make_uint2(pack_bf2(v.x - hx, v.y - hy), pack_bf2(v.z - hz, v.w - hw));
    uint32_t off = swz(r, q >> 1) + (uint32_t)(q & 1) * 8;
    *(uint2*)(hiB + off) = hi;
    *(uint2*)(loB + off) = lo;
}

__global__ __launch_bounds__(BLOCK_THREADS, 1) void meanpool_kernel(
    const void* __restrict__ neighbors_raw,
    const float* __restrict__ emb_table,
    const float* __restrict__ W,
    const float* __restrict__ b,
    float* __restrict__ out,
    int n_nodes)
{
    extern __shared__ char s[];
    float* Hs = (float*)(s + H_OFF);
    float* sB = (float*)(s + B_OFF);
    const uint32_t sbase = smem_u32(s);

    const int tid  = threadIdx.x;
    const int wid  = tid >> 5;
    const int lane = tid & 31;
    const int warp_m = wid & 3;     // 32-row block
    const int warp_n = wid >> 2;    // 64-col block
    const int is64 = g_idx_is64;

    // ---- Stage W (bf16 hi/lo, swizzled) + bias; zero-pad E rows 125..127 ----
    const float4* __restrict__ W4 = (const float4*)W;
    for (int i = tid; i < FDIM * 32; i += BLOCK_THREADS) {
        int f = i >> 5, q = i & 31;
        store_split(s + W_HI_OFF, s + W_LO_OFF, f, q, __ldg(&W4[f * 32 + q]));
    }
    for (int i = tid; i < 3 * 32; i += BLOCK_THREADS) {
        int r = ROWS_PER_TILE + (i >> 5), q = i & 31;
        store_split(s + E_HI_OFF, s + E_LO_OFF, r, q, make_float4(0.f, 0.f, 0.f, 0.f));
    }
    if (tid < FDIM) sB[tid] = __ldg(&b[tid]);
    __syncthreads();

    const int* __restrict__       nb32 = (const int*)neighbors_raw;
    const long long* __restrict__ nb64 = (const long long*)neighbors_raw;
    const float4* __restrict__ table4 = (const float4*)emb_table;

    const long long total_rows = (long long)n_nodes * S_SAMPLES;
    const int n_tiles = (int)((total_rows + ROWS_PER_TILE - 1) / ROWS_PER_TILE);

    for (int tile = blockIdx.x; tile < n_tiles; tile += GRID_BLOCKS) {
        const long long row_base = (long long)tile * ROWS_PER_TILE;

        // ---- gather 125 rows -> bf16 hi/lo split ----
        #pragma unroll 4
        for (int i = tid; i < ROWS_PER_TILE * 32; i += BLOCK_THREADS) {
            int r = i >> 5, q = i & 31;
            long long gr = row_base + r;
            float4 v = make_float4(0.f, 0.f, 0.f, 0.f);
            if (gr < total_rows) {
                long long nb = is64 ? __ldg(&nb64[gr]) : (long long)__ldg(&nb32[gr]);
                nb = nb < 0 ? 0 : (nb >= TABLE_SIZE ? TABLE_SIZE - 1 : nb);
                v = __ldg(&table4[nb * 32 + q]);
            }
            store_split(s + E_HI_OFF, s + E_LO_OFF, r, q, v);
        }
        __syncthreads();

        // ---- 3-split HMMA: each warp 32x64 output ----
        float acc[2][8][4];
        #pragma unroll
        for (int fm = 0; fm < 2; ++fm)
            #pragma unroll
            for (int fn = 0; fn < 8; ++fn)
                #pragma unroll
                for (int j = 0; j < 4; ++j) acc[fm][fn][j] = 0.0f;

        const int lrow = lane & 15;      // ldmatrix row within m16
        const int lmat = lane >> 4;      // ldmatrix k-chunk select
        const int bn   = lane >> 2;      // B fragment n-row within n8
        const int bk4  = (lane & 3) * 4; // B byte offset within 16B chunk

        #pragma unroll 1
        for (int t = 0; t < 3; ++t) {
            const uint32_t Asm = sbase + (t == 2 ? E_LO_OFF : E_HI_OFF);
            const char*    Bb  = s + (t == 1 ? W_LO_OFF : W_HI_OFF);

            #pragma unroll
            for (int ks = 0; ks < 8; ++ks) {
                uint32_t aF[2][4];
                #pragma unroll
                for (int fm = 0; fm < 2; ++fm) {
                    int row = warp_m * 32 + fm * 16 + lrow;
                    ldm_x4(aF[fm], Asm + swz(row, ks * 2 + lmat));
                }
                #pragma unroll
                for (int fn = 0; fn < 8; ++fn) {
                    int n = warp_n * 64 + fn * 8 + bn;
                    uint32_t b0 = *(const uint32_t*)(Bb + swz(n, ks * 2)     + bk4);
                    uint32_t b1 = *(const uint32_t*)(Bb + swz(n, ks * 2 + 1) + bk4);
                    mma_bf16(acc[0][fn], aF[0], b0, b1);
                    mma_bf16(acc[1][fn], aF[1], b0, b1);
                }
            }
        }

        // ---- epilogue: bias+relu into H, pool 25 rows, store ----
        #pragma unroll
        for (int fm = 0; fm < 2; ++fm) {
            int r0 = warp_m * 32 + fm * 16 + (lane >> 2);
            #pragma unroll
            for (int fn = 0; fn < 8; ++fn) {
                int c0 = warp_n * 64 + fn * 8 + (lane & 3) * 2;
                float bb0 = sB[c0], bb1 = sB[c0 + 1];
                Hs[r0 * H_STRIDE + c0]           = fmaxf(acc[fm][fn][0] + bb0, 0.f);
                Hs[r0 * H_STRIDE + c0 + 1]       = fmaxf(acc[fm][fn][1] + bb1, 0.f);
                Hs[(r0 + 8) * H_STRIDE + c0]     = fmaxf(acc[fm][fn][2] + bb0, 0.f);
                Hs[(r0 + 8) * H_STRIDE + c0 + 1] = fmaxf(acc[fm][fn][3] + bb1, 0.f);
            }
        }
        __syncthreads();

        for (int idx = tid; idx < NODES_PER_TILE * FDIM; idx += BLOCK_THREADS) {
            int g = idx >> 7, f = idx & 127;
            long long n = (long long)tile * NODES_PER_TILE + g;
            if (n < n_nodes) {
                float sum = 0.0f;
                #pragma unroll
                for (int ss = 0; ss < S_SAMPLES; ++ss)
                    sum += Hs[(g * S_SAMPLES + ss) * H_STRIDE + f];
                out[n * FDIM + f] = sum * (1.0f / S_SAMPLES);
            }
        }
        __syncthreads();   // protect E/H before next tile overwrites
    }
}

extern "C" void kernel_launch(void* const* d_in, const int* in_sizes, int n_in,
                              void* d_out, int out_size) {
    const void*  neighbors = d_in[0];
    const float* emb_table = (const float*)d_in[1];
    const float* W         = (const float*)d_in[2];
    const float* b         = (const float*)d_in[3];
    float*       out       = (float*)d_out;

    const int n_nodes = in_sizes[0] / S_SAMPLES;

    cudaFuncSetAttribute(meanpool_kernel,
                         cudaFuncAttributeMaxDynamicSharedMemorySize, SMEM_TOTAL);

    detect_idx_dtype<<<1, 1>>>((const int*)neighbors);
    meanpool_kernel<<<GRID_BLOCKS, BLOCK_THREADS, SMEM_TOTAL>>>(
        neighbors, emb_table, W, b, out, n_nodes);
}

// round 6
// speedup vs baseline: 4.1612x; 1.9747x over previous
#include <cuda_runtime.h>
#include <cuda_bf16.h>
#include <cstdint>

// out[n,f] = (1/25) * sum_s relu( dot(E[nbr[n,s],:], W[f,:]) + b[f] )
// bf16 3-split HMMA (mma.sync m16n8k16), persistent grid=148 x 512 threads.
// cp.async pipelines next tile's raw fp32 gather under current tile's MMA.
// H (fp32, XOR-swizzled) aliases the dead E bf16 buffers.

#define S_SAMPLES 25
#define FDIM 128
#define TABLE_SIZE 100000
#define ROWS_PER_TILE 125          // 5 nodes; 10000 tiles exactly
#define NODES_PER_TILE 5
#define BLOCK_THREADS 512
#define GRID_BLOCKS 148

#define E_HI_OFF 0                  // [128][256B] bf16, swizzled
#define E_LO_OFF 32768
#define W_HI_OFF 65536
#define W_LO_OFF 98304
#define RAW_OFF  131072             // [125][512B] fp32, linear
#define B_OFF    (RAW_OFF + 64000)  // 195072
#define SMEM_TOTAL (B_OFF + 512 + 16)
// H (64KB fp32) aliases [E_HI | E_LO]

__device__ int g_idx_is64;

__global__ void detect_idx_dtype(const int* __restrict__ nb32) {
    int is64 = 1;
    #pragma unroll
    for (int i = 1; i < 64; i += 2) if (nb32[i] != 0) is64 = 0;
    g_idx_is64 = is64;
}

// ---------------- helpers ----------------
__device__ __forceinline__ uint32_t smem_u32(const void* p) {
    uint32_t a;
    asm("{ .reg .u64 t; cvta.to.shared.u64 t, %1; cvt.u32.u64 %0, t; }" : "=r"(a) : "l"(p));
    return a;
}
// bf16 tile swizzle: 256B rows, 16B chunk ^ (row&7)
__device__ __forceinline__ uint32_t swz(int row, int chunk) {
    return (uint32_t)row * 256u + (uint32_t)(((chunk ^ (row & 7)) & 15) * 16);
}
// H swizzle: 512B fp32 rows, 16B chunk ^ (row&31)
__device__ __forceinline__ uint32_t hswz(int row, int cc) {
    return (uint32_t)row * 512u + (uint32_t)(((cc ^ (row & 31)) & 31) * 16);
}
__device__ __forceinline__ void ldm_x4(uint32_t* a, uint32_t addr) {
    asm volatile("ldmatrix.sync.aligned.m8n8.x4.shared.b16 {%0,%1,%2,%3}, [%4];"
                 : "=r"(a[0]), "=r"(a[1]), "=r"(a[2]), "=r"(a[3]) : "r"(addr));
}
__device__ __forceinline__ void mma_bf16(float* d, const uint32_t* a,
                                         uint32_t b0, uint32_t b1) {
    asm volatile(
        "mma.sync.aligned.m16n8k16.row.col.f32.bf16.bf16.f32 "
        "{%0,%1,%2,%3}, {%4,%5,%6,%7}, {%8,%9}, {%0,%1,%2,%3};"
        : "+f"(d[0]), "+f"(d[1]), "+f"(d[2]), "+f"(d[3])
        : "r"(a[0]), "r"(a[1]), "r"(a[2]), "r"(a[3]), "r"(b0), "r"(b1));
}
__device__ __forceinline__ uint32_t pack_bf2(float a, float b) {
    uint32_t r;
    asm("{ .reg .b16 lo, hi; cvt.rn.bf16.f32 lo, %1; cvt.rn.bf16.f32 hi, %2;"
        " mov.b32 %0, {lo, hi}; }" : "=r"(r) : "f"(a), "f"(b));
    return r;
}
__device__ __forceinline__ float bf_trunc(float x) {
    uint32_t r;
    asm("{ .reg .b16 t; cvt.rn.bf16.f32 t, %1; mov.b32 %0, {t, 0}; }" : "=r"(r) : "f"(x));
    return __uint_as_float(r << 16);
}
__device__ __forceinline__ void store_split(char* hiB, char* loB, int r, int q, float4 v) {
    float hx = bf_trunc(v.x), hy = bf_trunc(v.y), hz = bf_trunc(v.z), hw = bf_trunc(v.w);
    uint2 hi = make_uint2(pack_bf2(hx, hy), pack_bf2(hz, hw));
    uint2 lo = make_uint2(pack_bf2(v.x - hx, v.y - hy), pack_bf2(v.z - hz, v.w - hw));
    uint32_t off = swz(r, q >> 1) + (uint32_t)(q & 1) * 8;
    *(uint2*)(hiB + off) = hi;
    *(uint2*)(loB + off) = lo;
}
__device__ __forceinline__ void cp16(uint32_t dst, const void* src) {
    asm volatile("cp.async.cg.shared.global [%0], [%1], 16;" :: "r"(dst), "l"(src) : "memory");
}

// prefetch tile's 125 rows (raw fp32) via cp.async into RAW
__device__ __forceinline__ void prefetch_tile(
    uint32_t raw_base, long long row_base, int tid, int is64,
    const int* nb32, const long long* nb64, const float4* table4)
{
    long long nbuf[8];
    int cnt = 0;
    #pragma unroll
    for (int i = tid; i < ROWS_PER_TILE * 32; i += BLOCK_THREADS) {
        int r = i >> 5;
        long long gr = row_base + r;
        long long nb = is64 ? __ldg(&nb64[gr]) : (long long)__ldg(&nb32[gr]);
        nbuf[cnt++] = nb < 0 ? 0 : (nb >= TABLE_SIZE ? TABLE_SIZE - 1 : nb);
    }
    cnt = 0;
    #pragma unroll
    for (int i = tid; i < ROWS_PER_TILE * 32; i += BLOCK_THREADS) {
        int r = i >> 5, q = i & 31;
        cp16(raw_base + (uint32_t)r * 512u + (uint32_t)q * 16u,
             table4 + nbuf[cnt++] * 32 + q);
    }
    asm volatile("cp.async.commit_group;" ::: "memory");
}

__global__ __launch_bounds__(BLOCK_THREADS, 1) void meanpool_kernel(
    const void* __restrict__ neighbors_raw,
    const float* __restrict__ emb_table,
    const float* __restrict__ W,
    const float* __restrict__ b,
    float* __restrict__ out,
    int n_nodes)
{
    extern __shared__ char s[];
    const uint32_t sbase = smem_u32(s);
    float* sB = (float*)(s + B_OFF);

    const int tid  = threadIdx.x;
    const int wid  = tid >> 5;
    const int lane = tid & 31;
    const int warp_m = wid & 3;      // 32-row block
    const int warp_n = wid >> 2;     // 32-col block
    const int is64 = g_idx_is64;

    // ---- Stage W (bf16 hi/lo, swizzled) + bias, once ----
    const float4* __restrict__ W4 = (const float4*)W;
    for (int i = tid; i < FDIM * 32; i += BLOCK_THREADS) {
        int f = i >> 5, q = i & 31;
        store_split(s + W_HI_OFF, s + W_LO_OFF, f, q, __ldg(&W4[f * 32 + q]));
    }
    if (tid < FDIM) sB[tid] = __ldg(&b[tid]);

    const int* __restrict__       nb32 = (const int*)neighbors_raw;
    const long long* __restrict__ nb64 = (const long long*)neighbors_raw;
    const float4* __restrict__ table4 = (const float4*)emb_table;

    const int n_tiles = (int)(((long long)n_nodes * S_SAMPLES + ROWS_PER_TILE - 1)
                              / ROWS_PER_TILE);
    const float4* __restrict__ raw4 = (const float4*)(s + RAW_OFF);

    // ---- prologue: prefetch first tile ----
    if (blockIdx.x < n_tiles)
        prefetch_tile(sbase + RAW_OFF, (long long)blockIdx.x * ROWS_PER_TILE,
                      tid, is64, nb32, nb64, table4);

    // per-lane ldmatrix address components
    const int a_row = (lane & 15);          // + fm*16 + warp_m*32
    const int a_kc  = lane >> 4;            // 0/1 k-chunk
    const int b_n   = (lane & 7);           // + fsel*8 + fnpair*16 + warp_n*32
    const int b_kc  = (lane >> 3) & 1;
    const int b_fs  = lane >> 4;

    for (int tile = blockIdx.x; tile < n_tiles; tile += GRID_BLOCKS) {
        // ---- wait raw, convert fp32 -> bf16 hi/lo (rows 125-127 zeroed) ----
        asm volatile("cp.async.wait_group 0;" ::: "memory");
        __syncthreads();
        #pragma unroll
        for (int i = tid; i < 128 * 32; i += BLOCK_THREADS) {
            int r = i >> 5, q = i & 31;
            float4 v = (r < ROWS_PER_TILE) ? raw4[r * 32 + q]
                                           : make_float4(0.f, 0.f, 0.f, 0.f);
            store_split(s + E_HI_OFF, s + E_LO_OFF, r, q, v);
        }
        __syncthreads();

        // ---- prefetch next tile under the MMA ----
        int ntile = tile + GRID_BLOCKS;
        if (ntile < n_tiles)
            prefetch_tile(sbase + RAW_OFF, (long long)ntile * ROWS_PER_TILE,
                          tid, is64, nb32, nb64, table4);

        // ---- 3-split HMMA, single ks pass: EhiWhi + EhiWlo + EloWhi ----
        float acc[2][4][4];
        #pragma unroll
        for (int fm = 0; fm < 2; ++fm)
            #pragma unroll
            for (int fn = 0; fn < 4; ++fn)
                #pragma unroll
                for (int j = 0; j < 4; ++j) acc[fm][fn][j] = 0.0f;

        #pragma unroll
        for (int ks = 0; ks < 8; ++ks) {
            uint32_t aHi[2][4], aLo[2][4], bHi[8], bLo[8];
            #pragma unroll
            for (int fm = 0; fm < 2; ++fm) {
                int row = warp_m * 32 + fm * 16 + a_row;
                ldm_x4(aHi[fm], sbase + E_HI_OFF + swz(row, ks * 2 + a_kc));
                ldm_x4(aLo[fm], sbase + E_LO_OFF + swz(row, ks * 2 + a_kc));
            }
            #pragma unroll
            for (int fp = 0; fp < 2; ++fp) {   // fn pairs {0,1},{2,3}
                int n = warp_n * 32 + fp * 16 + b_fs * 8 + b_n;
                ldm_x4(bHi + fp * 4, sbase + W_HI_OFF + swz(n, ks * 2 + b_kc));
                ldm_x4(bLo + fp * 4, sbase + W_LO_OFF + swz(n, ks * 2 + b_kc));
            }
            #pragma unroll
            for (int fm = 0; fm < 2; ++fm)
                #pragma unroll
                for (int fn = 0; fn < 4; ++fn) {
                    mma_bf16(acc[fm][fn], aHi[fm], bHi[fn * 2], bHi[fn * 2 + 1]);
                    mma_bf16(acc[fm][fn], aHi[fm], bLo[fn * 2], bLo[fn * 2 + 1]);
                    mma_bf16(acc[fm][fn], aLo[fm], bHi[fn * 2], bHi[fn * 2 + 1]);
                }
        }
        __syncthreads();   // all E reads done before H aliases it

        // ---- bias+relu -> H (aliases E, hswz) ----
        #pragma unroll
        for (int fm = 0; fm < 2; ++fm) {
            int r0 = warp_m * 32 + fm * 16 + (lane >> 2);
            #pragma unroll
            for (int fn = 0; fn < 4; ++fn) {
                int c0 = warp_n * 32 + fn * 8 + (lane & 3) * 2;
                int cc = c0 >> 2, byo = (c0 & 3) * 4;
                float bb0 = sB[c0], bb1 = sB[c0 + 1];
                float2 v0 = make_float2(fmaxf(acc[fm][fn][0] + bb0, 0.f),
                                        fmaxf(acc[fm][fn][1] + bb1, 0.f));
                float2 v1 = make_float2(fmaxf(acc[fm][fn][2] + bb0, 0.f),
                                        fmaxf(acc[fm][fn][3] + bb1, 0.f));
                *(float2*)(s + hswz(r0, cc) + byo)     = v0;
                *(float2*)(s + hswz(r0 + 8, cc) + byo) = v1;
            }
        }
        __syncthreads();

        // ---- pool 25 rows per node, vectorized store ----
        for (int i = tid; i < NODES_PER_TILE * 32; i += BLOCK_THREADS) {
            int g = i >> 5, f4 = i & 31;
            float4 sum = make_float4(0.f, 0.f, 0.f, 0.f);
            #pragma unroll
            for (int ss = 0; ss < S_SAMPLES; ++ss) {
                float4 v = *(const float4*)(s + hswz(g * S_SAMPLES + ss, f4));
                sum.x += v.x; sum.y += v.y; sum.z += v.z; sum.w += v.w;
            }
            long long n = (long long)tile * NODES_PER_TILE + g;
            if (n < n_nodes) {
                sum.x *= (1.0f / S_SAMPLES); sum.y *= (1.0f / S_SAMPLES);
                sum.z *= (1.0f / S_SAMPLES); sum.w *= (1.0f / S_SAMPLES);
                ((float4*)out)[n * 32 + f4] = sum;
            }
        }
        __syncthreads();   // H dead before next convert overwrites
    }
}

extern "C" void kernel_launch(void* const* d_in, const int* in_sizes, int n_in,
                              void* d_out, int out_size) {
    const void*  neighbors = d_in[0];
    const float* emb_table = (const float*)d_in[1];
    const float* W         = (const float*)d_in[2];
    const float* b         = (const float*)d_in[3];
    float*       out       = (float*)d_out;

    const int n_nodes = in_sizes[0] / S_SAMPLES;

    cudaFuncSetAttribute(meanpool_kernel,
                         cudaFuncAttributeMaxDynamicSharedMemorySize, SMEM_TOTAL);

    detect_idx_dtype<<<1, 1>>>((const int*)neighbors);
    meanpool_kernel<<<GRID_BLOCKS, BLOCK_THREADS, SMEM_TOTAL>>>(
        neighbors, emb_table, W, b, out, n_nodes);
}

// round 7
// speedup vs baseline: 4.9117x; 1.1804x over previous
#include <cuda_runtime.h>
#include <cuda_fp16.h>
#include <cstdint>

// out[n,f] = (1/25) * sum_s relu( dot(E[nbr[n,s],:], W[f,:]) + b[f] )
// fp16 2-term split HMMA: E = Ehi + Elo (f16 each, ~22 bits), W rounded to one
// f16 -> D = Ehi@W + Elo@W = E@Wf16 in fp32 accum (err ~1e-4 rel, gate 1e-3).
// Persistent grid=148 x 512 thr, cp.async pipelines next tile's raw gather
// under the MMA. H (fp32, XOR-swizzled) aliases the dead E buffers.

#define S_SAMPLES 25
#define FDIM 128
#define TABLE_SIZE 100000
#define ROWS_PER_TILE 125          // 5 nodes; 10000 tiles exactly
#define NODES_PER_TILE 5
#define BLOCK_THREADS 512
#define GRID_BLOCKS 148

#define E_HI_OFF 0                  // [128][256B] f16, swizzled
#define E_LO_OFF 32768
#define W_OFF    65536              // [128][256B] f16, swizzled
#define RAW_OFF  98304              // [125][512B] fp32, linear
#define B_OFF    (RAW_OFF + 64000)  // 162304
#define SMEM_TOTAL (B_OFF + 512 + 16)
// H (64KB fp32) aliases [E_HI | E_LO]

__device__ int g_idx_is64;

__global__ void detect_idx_dtype(const int* __restrict__ nb32) {
    int is64 = 1;
    #pragma unroll
    for (int i = 1; i < 64; i += 2) if (nb32[i] != 0) is64 = 0;
    g_idx_is64 = is64;
}

// ---------------- helpers ----------------
__device__ __forceinline__ uint32_t smem_u32(const void* p) {
    uint32_t a;
    asm("{ .reg .u64 t; cvta.to.shared.u64 t, %1; cvt.u32.u64 %0, t; }" : "=r"(a) : "l"(p));
    return a;
}
// f16 tile swizzle: 256B rows, 16B chunk ^ (row&7)
__device__ __forceinline__ uint32_t swz(int row, int chunk) {
    return (uint32_t)row * 256u + (uint32_t)(((chunk ^ (row & 7)) & 15) * 16);
}
// H swizzle: 512B fp32 rows, 16B chunk ^ (row&31)
__device__ __forceinline__ uint32_t hswz(int row, int cc) {
    return (uint32_t)row * 512u + (uint32_t)(((cc ^ (row & 31)) & 31) * 16);
}
__device__ __forceinline__ void ldm_x4(uint32_t* a, uint32_t addr) {
    asm volatile("ldmatrix.sync.aligned.m8n8.x4.shared.b16 {%0,%1,%2,%3}, [%4];"
                 : "=r"(a[0]), "=r"(a[1]), "=r"(a[2]), "=r"(a[3]) : "r"(addr));
}
__device__ __forceinline__ void mma_f16(float* d, const uint32_t* a,
                                        uint32_t b0, uint32_t b1) {
    asm volatile(
        "mma.sync.aligned.m16n8k16.row.col.f32.f16.f16.f32 "
        "{%0,%1,%2,%3}, {%4,%5,%6,%7}, {%8,%9}, {%0,%1,%2,%3};"
        : "+f"(d[0]), "+f"(d[1]), "+f"(d[2]), "+f"(d[3])
        : "r"(a[0]), "r"(a[1]), "r"(a[2]), "r"(a[3]), "r"(b0), "r"(b1));
}
// two floats -> packed f16 hi parts + packed f16 residuals
__device__ __forceinline__ void split2(float a, float b, uint32_t& hi, uint32_t& lo) {
    asm("{ .reg .b16 ha, hb, la, lb; .reg .f32 ra, rb;\n\t"
        "cvt.rn.f16.f32 ha, %2; cvt.rn.f16.f32 hb, %3;\n\t"
        "cvt.f32.f16 ra, ha; cvt.f32.f16 rb, hb;\n\t"
        "sub.f32 ra, %2, ra; sub.f32 rb, %3, rb;\n\t"
        "cvt.rn.f16.f32 la, ra; cvt.rn.f16.f32 lb, rb;\n\t"
        "mov.b32 %0, {ha, hb}; mov.b32 %1, {la, lb}; }"
        : "=r"(hi), "=r"(lo) : "f"(a), "f"(b));
}
__device__ __forceinline__ uint32_t pack_h2(float a, float b) {
    uint32_t r;
    asm("{ .reg .b16 x, y; cvt.rn.f16.f32 x, %1; cvt.rn.f16.f32 y, %2;"
        " mov.b32 %0, {x, y}; }" : "=r"(r) : "f"(a), "f"(b));
    return r;
}
__device__ __forceinline__ void cp16(uint32_t dst, const void* src) {
    asm volatile("cp.async.cg.shared.global [%0], [%1], 16;" :: "r"(dst), "l"(src) : "memory");
}

// prefetch tile's 125 rows (raw fp32) via cp.async into RAW
__device__ __forceinline__ void prefetch_tile(
    uint32_t raw_base, long long row_base, int tid, int is64,
    const int* nb32, const long long* nb64, const float4* table4)
{
    long long nbuf[8];
    int cnt = 0;
    #pragma unroll
    for (int i = tid; i < ROWS_PER_TILE * 32; i += BLOCK_THREADS) {
        int r = i >> 5;
        long long gr = row_base + r;
        long long nb = is64 ? __ldg(&nb64[gr]) : (long long)__ldg(&nb32[gr]);
        nbuf[cnt++] = nb < 0 ? 0 : (nb >= TABLE_SIZE ? TABLE_SIZE - 1 : nb);
    }
    cnt = 0;
    #pragma unroll
    for (int i = tid; i < ROWS_PER_TILE * 32; i += BLOCK_THREADS) {
        int r = i >> 5, q = i & 31;
        cp16(raw_base + (uint32_t)r * 512u + (uint32_t)q * 16u,
             table4 + nbuf[cnt++] * 32 + q);
    }
    asm volatile("cp.async.commit_group;" ::: "memory");
}

__global__ __launch_bounds__(BLOCK_THREADS, 1) void meanpool_kernel(
    const void* __restrict__ neighbors_raw,
    const float* __restrict__ emb_table,
    const float* __restrict__ W,
    const float* __restrict__ b,
    float* __restrict__ out,
    int n_nodes)
{
    extern __shared__ char s[];
    const uint32_t sbase = smem_u32(s);
    float* sB = (float*)(s + B_OFF);

    const int tid  = threadIdx.x;
    const int wid  = tid >> 5;
    const int lane = tid & 31;
    const int warp_m = wid & 3;      // 32-row block
    const int warp_n = wid >> 2;     // 32-col block
    const int is64 = g_idx_is64;

    // ---- Stage W (single f16, swizzled) + bias, once ----
    const float4* __restrict__ W4 = (const float4*)W;
    for (int i = tid; i < FDIM * 16; i += BLOCK_THREADS) {
        int f = i >> 4, c = i & 15;
        float4 v0 = __ldg(&W4[f * 32 + 2 * c]);
        float4 v1 = __ldg(&W4[f * 32 + 2 * c + 1]);
        uint4 w;
        w.x = pack_h2(v0.x, v0.y); w.y = pack_h2(v0.z, v0.w);
        w.z = pack_h2(v1.x, v1.y); w.w = pack_h2(v1.z, v1.w);
        *(uint4*)(s + W_OFF + swz(f, c)) = w;
    }
    if (tid < FDIM) sB[tid] = __ldg(&b[tid]);

    const int* __restrict__       nb32 = (const int*)neighbors_raw;
    const long long* __restrict__ nb64 = (const long long*)neighbors_raw;
    const float4* __restrict__ table4 = (const float4*)emb_table;

    const int n_tiles = (int)(((long long)n_nodes * S_SAMPLES + ROWS_PER_TILE - 1)
                              / ROWS_PER_TILE);
    const float4* __restrict__ raw4 = (const float4*)(s + RAW_OFF);

    // ---- prologue: prefetch first tile ----
    if (blockIdx.x < n_tiles)
        prefetch_tile(sbase + RAW_OFF, (long long)blockIdx.x * ROWS_PER_TILE,
                      tid, is64, nb32, nb64, table4);

    // per-lane ldmatrix address components
    const int a_row = (lane & 15);
    const int a_kc  = lane >> 4;
    const int b_n   = (lane & 7);
    const int b_kc  = (lane >> 3) & 1;
    const int b_fs  = lane >> 4;

    for (int tile = blockIdx.x; tile < n_tiles; tile += GRID_BLOCKS) {
        // ---- wait raw, convert fp32 -> f16 hi/lo (rows 125-127 zeroed) ----
        asm volatile("cp.async.wait_group 0;" ::: "memory");
        __syncthreads();
        #pragma unroll
        for (int i = tid; i < 128 * 16; i += BLOCK_THREADS) {
            int r = i >> 4, c = i & 15;
            float4 v0 = make_float4(0.f, 0.f, 0.f, 0.f), v1 = v0;
            if (r < ROWS_PER_TILE) {
                v0 = raw4[r * 32 + 2 * c];
                v1 = raw4[r * 32 + 2 * c + 1];
            }
            uint4 hi, lo;
            split2(v0.x, v0.y, hi.x, lo.x);
            split2(v0.z, v0.w, hi.y, lo.y);
            split2(v1.x, v1.y, hi.z, lo.z);
            split2(v1.z, v1.w, hi.w, lo.w);
            uint32_t o = swz(r, c);
            *(uint4*)(s + E_HI_OFF + o) = hi;
            *(uint4*)(s + E_LO_OFF + o) = lo;
        }
        __syncthreads();

        // ---- prefetch next tile under the MMA ----
        int ntile = tile + GRID_BLOCKS;
        if (ntile < n_tiles)
            prefetch_tile(sbase + RAW_OFF, (long long)ntile * ROWS_PER_TILE,
                          tid, is64, nb32, nb64, table4);

        // ---- 2-term HMMA: Ehi@W + Elo@W ----
        float acc[2][4][4];
        #pragma unroll
        for (int fm = 0; fm < 2; ++fm)
            #pragma unroll
            for (int fn = 0; fn < 4; ++fn)
                #pragma unroll
                for (int j = 0; j < 4; ++j) acc[fm][fn][j] = 0.0f;

        #pragma unroll
        for (int ks = 0; ks < 8; ++ks) {
            uint32_t aHi[2][4], aLo[2][4], bW[8];
            #pragma unroll
            for (int fm = 0; fm < 2; ++fm) {
                int row = warp_m * 32 + fm * 16 + a_row;
                ldm_x4(aHi[fm], sbase + E_HI_OFF + swz(row, ks * 2 + a_kc));
                ldm_x4(aLo[fm], sbase + E_LO_OFF + swz(row, ks * 2 + a_kc));
            }
            #pragma unroll
            for (int fp = 0; fp < 2; ++fp) {
                int n = warp_n * 32 + fp * 16 + b_fs * 8 + b_n;
                ldm_x4(bW + fp * 4, sbase + W_OFF + swz(n, ks * 2 + b_kc));
            }
            #pragma unroll
            for (int fm = 0; fm < 2; ++fm)
                #pragma unroll
                for (int fn = 0; fn < 4; ++fn) {
                    mma_f16(acc[fm][fn], aHi[fm], bW[fn * 2], bW[fn * 2 + 1]);
                    mma_f16(acc[fm][fn], aLo[fm], bW[fn * 2], bW[fn * 2 + 1]);
                }
        }
        __syncthreads();   // all E reads done before H aliases it

        // ---- bias+relu -> H (aliases E, hswz) ----
        #pragma unroll
        for (int fm = 0; fm < 2; ++fm) {
            int r0 = warp_m * 32 + fm * 16 + (lane >> 2);
            #pragma unroll
            for (int fn = 0; fn < 4; ++fn) {
                int c0 = warp_n * 32 + fn * 8 + (lane & 3) * 2;
                int cc = c0 >> 2, byo = (c0 & 3) * 4;
                float bb0 = sB[c0], bb1 = sB[c0 + 1];
                float2 v0 = make_float2(fmaxf(acc[fm][fn][0] + bb0, 0.f),
                                        fmaxf(acc[fm][fn][1] + bb1, 0.f));
                float2 v1 = make_float2(fmaxf(acc[fm][fn][2] + bb0, 0.f),
                                        fmaxf(acc[fm][fn][3] + bb1, 0.f));
                *(float2*)(s + hswz(r0, cc) + byo)     = v0;
                *(float2*)(s + hswz(r0 + 8, cc) + byo) = v1;
            }
        }
        __syncthreads();

        // ---- pool 25 rows per node, vectorized store ----
        for (int i = tid; i < NODES_PER_TILE * 32; i += BLOCK_THREADS) {
            int g = i >> 5, f4 = i & 31;
            float4 sum = make_float4(0.f, 0.f, 0.f, 0.f);
            #pragma unroll
            for (int ss = 0; ss < S_SAMPLES; ++ss) {
                float4 v = *(const float4*)(s + hswz(g * S_SAMPLES + ss, f4));
                sum.x += v.x; sum.y += v.y; sum.z += v.z; sum.w += v.w;
            }
            long long n = (long long)tile * NODES_PER_TILE + g;
            if (n < n_nodes) {
                sum.x *= (1.0f / S_SAMPLES); sum.y *= (1.0f / S_SAMPLES);
                sum.z *= (1.0f / S_SAMPLES); sum.w *= (1.0f / S_SAMPLES);
                ((float4*)out)[n * 32 + f4] = sum;
            }
        }
        __syncthreads();   // H dead before next convert overwrites
    }
}

extern "C" void kernel_launch(void* const* d_in, const int* in_sizes, int n_in,
                              void* d_out, int out_size) {
    const void*  neighbors = d_in[0];
    const float* emb_table = (const float*)d_in[1];
    const float* W         = (const float*)d_in[2];
    const float* b         = (const float*)d_in[3];
    float*       out       = (float*)d_out;

    const int n_nodes = in_sizes[0] / S_SAMPLES;

    cudaFuncSetAttribute(meanpool_kernel,
                         cudaFuncAttributeMaxDynamicSharedMemorySize, SMEM_TOTAL);

    detect_idx_dtype<<<1, 1>>>((const int*)neighbors);
    meanpool_kernel<<<GRID_BLOCKS, BLOCK_THREADS, SMEM_TOTAL>>>(
        neighbors, emb_table, W, b, out, n_nodes);
}

// round 8
// speedup vs baseline: 4.9175x; 1.0012x over previous
#include <cuda_runtime.h>
#include <cuda_fp16.h>
#include <cstdint>

// out[n,f] = (1/25) * sum_s relu( dot(E[nbr[n,s],:], W[f,:]) + b[f] )
// Single-term f16 HMMA (E,W rounded to f16, fp32 accum; rel_err ~1.3e-4 vs
// 1e-3 gate). Persistent grid=148 x 512 thr. M=256 tiles (10 nodes, 250 rows),
// 16 warps = 4m x 4n, warp tile 64x32. cp.async prefetches next tile's raw
// fp32 rows under the MMA. H (f16) aliases the dead E buffer.

#define S_SAMPLES 25
#define FDIM 128
#define TABLE_SIZE 100000
#define ROWS_PER_TILE 250
#define NODES_PER_TILE 10
#define M_PAD 256
#define BLOCK_THREADS 512
#define GRID_BLOCKS 148

#define E_OFF   0                   // [256][256B] f16, swizzled (aliased by H)
#define W_OFF   65536               // [128][256B] f16, swizzled
#define RAW_OFF 98304               // [250][512B] fp32, linear
#define B_OFF   226304              // bias 512B
#define SMEM_TOTAL 226832

__device__ int g_idx_is64;

__global__ void detect_idx_dtype(const int* __restrict__ nb32) {
    int is64 = 1;
    #pragma unroll
    for (int i = 1; i < 64; i += 2) if (nb32[i] != 0) is64 = 0;
    g_idx_is64 = is64;
}

// ---------------- helpers ----------------
__device__ __forceinline__ uint32_t smem_u32(const void* p) {
    uint32_t a;
    asm("{ .reg .u64 t; cvta.to.shared.u64 t, %1; cvt.u32.u64 %0, t; }" : "=r"(a) : "l"(p));
    return a;
}
// f16 tile swizzle: 256B rows, 16B chunk ^ (row&7)  (ldmatrix-compatible)
__device__ __forceinline__ uint32_t swz(int row, int chunk) {
    return (uint32_t)row * 256u + (uint32_t)(((chunk ^ (row & 7)) & 15) * 16);
}
// H swizzle: 256B f16 rows, 16B chunk ^ (row&15)
__device__ __forceinline__ uint32_t hswz(int row, int cc) {
    return (uint32_t)row * 256u + (uint32_t)(((cc ^ (row & 15)) & 15) * 16);
}
__device__ __forceinline__ void ldm_x4(uint32_t* a, uint32_t addr) {
    asm volatile("ldmatrix.sync.aligned.m8n8.x4.shared.b16 {%0,%1,%2,%3}, [%4];"
                 : "=r"(a[0]), "=r"(a[1]), "=r"(a[2]), "=r"(a[3]) : "r"(addr));
}
__device__ __forceinline__ void mma_f16(float* d, const uint32_t* a,
                                        uint32_t b0, uint32_t b1) {
    asm volatile(
        "mma.sync.aligned.m16n8k16.row.col.f32.f16.f16.f32 "
        "{%0,%1,%2,%3}, {%4,%5,%6,%7}, {%8,%9}, {%0,%1,%2,%3};"
        : "+f"(d[0]), "+f"(d[1]), "+f"(d[2]), "+f"(d[3])
        : "r"(a[0]), "r"(a[1]), "r"(a[2]), "r"(a[3]), "r"(b0), "r"(b1));
}
__device__ __forceinline__ uint32_t pack_h2(float a, float b) {
    uint32_t r;
    asm("{ .reg .b16 x, y; cvt.rn.f16.f32 x, %1; cvt.rn.f16.f32 y, %2;"
        " mov.b32 %0, {x, y}; }" : "=r"(r) : "f"(a), "f"(b));
    return r;
}
__device__ __forceinline__ float2 h2f2(uint32_t h) {
    float2 r;
    asm("{ .reg .b16 x, y; mov.b32 {x, y}, %2;"
        " cvt.f32.f16 %0, x; cvt.f32.f16 %1, y; }" : "=f"(r.x), "=f"(r.y) : "r"(h));
    return r;
}
__device__ __forceinline__ void cp16(uint32_t dst, const void* src) {
    asm volatile("cp.async.cg.shared.global [%0], [%1], 16;" :: "r"(dst), "l"(src) : "memory");
}

// prefetch tile's 250 raw fp32 rows via cp.async into RAW
__device__ __forceinline__ void prefetch_tile(
    uint32_t raw_base, long long row_base, long long total_rows, int tid, int is64,
    const int* nb32, const long long* nb64, const float4* table4)
{
    int nbuf[16];
    int cnt = 0;
    #pragma unroll
    for (int i = tid; i < ROWS_PER_TILE * 32; i += BLOCK_THREADS) {
        int r = i >> 5;
        long long gr = row_base + r;
        long long nb = 0;
        if (gr < total_rows)
            nb = is64 ? __ldg(&nb64[gr]) : (long long)__ldg(&nb32[gr]);
        nb = nb < 0 ? 0 : (nb >= TABLE_SIZE ? TABLE_SIZE - 1 : nb);
        nbuf[cnt++] = (int)nb;
    }
    cnt = 0;
    #pragma unroll
    for (int i = tid; i < ROWS_PER_TILE * 32; i += BLOCK_THREADS) {
        int r = i >> 5, q = i & 31;
        cp16(raw_base + (uint32_t)r * 512u + (uint32_t)q * 16u,
             table4 + (long long)nbuf[cnt++] * 32 + q);
    }
    asm volatile("cp.async.commit_group;" ::: "memory");
}

__global__ __launch_bounds__(BLOCK_THREADS, 1) void meanpool_kernel(
    const void* __restrict__ neighbors_raw,
    const float* __restrict__ emb_table,
    const float* __restrict__ W,
    const float* __restrict__ b,
    float* __restrict__ out,
    int n_nodes)
{
    extern __shared__ char s[];
    const uint32_t sbase = smem_u32(s);
    float* sB = (float*)(s + B_OFF);

    const int tid  = threadIdx.x;
    const int wid  = tid >> 5;
    const int lane = tid & 31;
    const int warp_m = wid & 3;      // 64-row block
    const int warp_n = wid >> 2;     // 32-col block
    const int is64 = g_idx_is64;

    // ---- Stage W (f16, swizzled) + bias, once ----
    const float4* __restrict__ W4 = (const float4*)W;
    for (int i = tid; i < FDIM * 16; i += BLOCK_THREADS) {
        int f = i >> 4, c = i & 15;
        float4 v0 = __ldg(&W4[f * 32 + 2 * c]);
        float4 v1 = __ldg(&W4[f * 32 + 2 * c + 1]);
        uint4 w;
        w.x = pack_h2(v0.x, v0.y); w.y = pack_h2(v0.z, v0.w);
        w.z = pack_h2(v1.x, v1.y); w.w = pack_h2(v1.z, v1.w);
        *(uint4*)(s + W_OFF + swz(f, c)) = w;
    }
    if (tid < FDIM) sB[tid] = __ldg(&b[tid]);
    __syncthreads();

    // per-thread bias registers for the epilogue
    float bb[4][2];
    #pragma unroll
    for (int fn = 0; fn < 4; ++fn) {
        int c0 = warp_n * 32 + fn * 8 + (lane & 3) * 2;
        bb[fn][0] = sB[c0];
        bb[fn][1] = sB[c0 + 1];
    }

    const int* __restrict__       nb32 = (const int*)neighbors_raw;
    const long long* __restrict__ nb64 = (const long long*)neighbors_raw;
    const float4* __restrict__ table4 = (const float4*)emb_table;

    const long long total_rows = (long long)n_nodes * S_SAMPLES;
    const int n_tiles = (int)((total_rows + ROWS_PER_TILE - 1) / ROWS_PER_TILE);
    const float4* __restrict__ raw4 = (const float4*)(s + RAW_OFF);

    // ---- prologue: prefetch first tile ----
    if (blockIdx.x < n_tiles)
        prefetch_tile(sbase + RAW_OFF, (long long)blockIdx.x * ROWS_PER_TILE,
                      total_rows, tid, is64, nb32, nb64, table4);

    // per-lane ldmatrix address components
    const int a_row = (lane & 15);
    const int a_kc  = lane >> 4;
    const int b_n   = (lane & 7);
    const int b_kc  = (lane >> 3) & 1;
    const int b_fs  = lane >> 4;

    for (int tile = blockIdx.x; tile < n_tiles; tile += GRID_BLOCKS) {
        // ---- wait raw, convert fp32 -> f16 (rows 250-255 zeroed) ----
        asm volatile("cp.async.wait_group 0;" ::: "memory");
        __syncthreads();
        #pragma unroll
        for (int i = tid; i < M_PAD * 16; i += BLOCK_THREADS) {
            int r = i >> 4, c = i & 15;
            float4 v0 = make_float4(0.f, 0.f, 0.f, 0.f), v1 = v0;
            if (r < ROWS_PER_TILE) {
                v0 = raw4[r * 32 + 2 * c];
                v1 = raw4[r * 32 + 2 * c + 1];
            }
            uint4 w;
            w.x = pack_h2(v0.x, v0.y); w.y = pack_h2(v0.z, v0.w);
            w.z = pack_h2(v1.x, v1.y); w.w = pack_h2(v1.z, v1.w);
            *(uint4*)(s + E_OFF + swz(r, c)) = w;
        }
        __syncthreads();

        // ---- prefetch next tile's raw rows under the MMA ----
        int ntile = tile + GRID_BLOCKS;
        if (ntile < n_tiles)
            prefetch_tile(sbase + RAW_OFF, (long long)ntile * ROWS_PER_TILE,
                          total_rows, tid, is64, nb32, nb64, table4);

        // ---- single-term HMMA: 64x32 per warp ----
        float acc[4][4][4];
        #pragma unroll
        for (int fm = 0; fm < 4; ++fm)
            #pragma unroll
            for (int fn = 0; fn < 4; ++fn)
                #pragma unroll
                for (int j = 0; j < 4; ++j) acc[fm][fn][j] = 0.0f;

        #pragma unroll
        for (int ks = 0; ks < 8; ++ks) {
            uint32_t aF[4][4], bW[8];
            #pragma unroll
            for (int fm = 0; fm < 4; ++fm) {
                int row = warp_m * 64 + fm * 16 + a_row;
                ldm_x4(aF[fm], sbase + E_OFF + swz(row, ks * 2 + a_kc));
            }
            #pragma unroll
            for (int fp = 0; fp < 2; ++fp) {
                int n = warp_n * 32 + fp * 16 + b_fs * 8 + b_n;
                ldm_x4(bW + fp * 4, sbase + W_OFF + swz(n, ks * 2 + b_kc));
            }
            #pragma unroll
            for (int fm = 0; fm < 4; ++fm)
                #pragma unroll
                for (int fn = 0; fn < 4; ++fn)
                    mma_f16(acc[fm][fn], aF[fm], bW[fn * 2], bW[fn * 2 + 1]);
        }
        __syncthreads();   // all E reads done before H aliases it

        // ---- bias+relu -> H (f16, aliases E) ----
        #pragma unroll
        for (int fm = 0; fm < 4; ++fm) {
            int r0 = warp_m * 64 + fm * 16 + (lane >> 2);
            #pragma unroll
            for (int fn = 0; fn < 4; ++fn) {
                int c0 = warp_n * 32 + fn * 8 + (lane & 3) * 2;
                int cc = c0 >> 3, byo = (c0 & 7) * 2;
                uint32_t h0 = pack_h2(fmaxf(acc[fm][fn][0] + bb[fn][0], 0.f),
                                      fmaxf(acc[fm][fn][1] + bb[fn][1], 0.f));
                uint32_t h1 = pack_h2(fmaxf(acc[fm][fn][2] + bb[fn][0], 0.f),
                                      fmaxf(acc[fm][fn][3] + bb[fn][1], 0.f));
                *(uint32_t*)(s + hswz(r0, cc) + byo)     = h0;
                *(uint32_t*)(s + hswz(r0 + 8, cc) + byo) = h1;
            }
        }
        __syncthreads();

        // ---- pool 25 rows per node (f16 H read, fp32 accumulate) ----
        for (int i = tid; i < NODES_PER_TILE * 32; i += BLOCK_THREADS) {
            int g = i >> 5, cc2 = i & 31;          // 8B units within row
            float4 sum = make_float4(0.f, 0.f, 0.f, 0.f);
            #pragma unroll
            for (int ss = 0; ss < S_SAMPLES; ++ss) {
                int row = g * S_SAMPLES + ss;
                uint2 v = *(const uint2*)(s + hswz(row, cc2 >> 1) + (cc2 & 1) * 8);
                float2 p0 = h2f2(v.x), p1 = h2f2(v.y);
                sum.x += p0.x; sum.y += p0.y; sum.z += p1.x; sum.w += p1.y;
            }
            long long n = (long long)tile * NODES_PER_TILE + g;
            if (n < n_nodes) {
                sum.x *= (1.0f / S_SAMPLES); sum.y *= (1.0f / S_SAMPLES);
                sum.z *= (1.0f / S_SAMPLES); sum.w *= (1.0f / S_SAMPLES);
                ((float4*)out)[n * 32 + cc2] = sum;
            }
        }
        __syncthreads();   // H dead before next convert overwrites
    }
}

extern "C" void kernel_launch(void* const* d_in, const int* in_sizes, int n_in,
                              void* d_out, int out_size) {
    const void*  neighbors = d_in[0];
    const float* emb_table = (const float*)d_in[1];
    const float* W         = (const float*)d_in[2];
    const float* b         = (const float*)d_in[3];
    float*       out       = (float*)d_out;

    const int n_nodes = in_sizes[0] / S_SAMPLES;

    cudaFuncSetAttribute(meanpool_kernel,
                         cudaFuncAttributeMaxDynamicSharedMemorySize, SMEM_TOTAL);

    detect_idx_dtype<<<1, 1>>>((const int*)neighbors);
    meanpool_kernel<<<GRID_BLOCKS, BLOCK_THREADS, SMEM_TOTAL>>>(
        neighbors, emb_table, W, b, out, n_nodes);
}

// round 9
// speedup vs baseline: 6.3522x; 1.2918x over previous
#include <cuda_runtime.h>
#include <cuda_fp16.h>
#include <cstdint>

// out[n,f] = (1/25) * sum_s relu( dot(E[nbr[n,s],:], W[f,:]) + b[f] )
// f16 HMMA (fp32 accum). The embedding table is pre-converted to f16 into a
// __device__ global once per launch; the gather then cp.asyncs f16 chunks
// directly into the swizzled, double-buffered E tile (no raw fp32 staging, no
// convert phase). M=256 tiles (10 nodes), 16 warps = 4m x 4n. H (f16) aliases
// the consumed E buffer for the fused bias+relu+meanpool epilogue.

#define S_SAMPLES 25
#define FDIM 128
#define TABLE_SIZE 100000
#define ROWS_PER_TILE 250
#define NODES_PER_TILE 10
#define M_PAD 256
#define BLOCK_THREADS 512
#define GRID_BLOCKS 148

#define E0_OFF 0                    // [256][256B] f16, swizzled (double buffer)
#define E1_OFF 65536
#define W_OFF  131072               // [128][256B] f16, swizzled
#define B_OFF  163840               // bias 512B
#define SMEM_TOTAL 164864

__device__ int g_idx_is64;
__device__ uint4 g_tab16[TABLE_SIZE * 16];   // f16 table mirror, 16B chunks

__global__ void detect_idx_dtype(const int* __restrict__ nb32) {
    int is64 = 1;
    #pragma unroll
    for (int i = 1; i < 64; i += 2) if (nb32[i] != 0) is64 = 0;
    g_idx_is64 = is64;
}

__device__ __forceinline__ uint32_t pack_h2(float a, float b) {
    uint32_t r;
    asm("{ .reg .b16 x, y; cvt.rn.f16.f32 x, %1; cvt.rn.f16.f32 y, %2;"
        " mov.b32 %0, {x, y}; }" : "=r"(r) : "f"(a), "f"(b));
    return r;
}

// fp32 table -> f16 mirror (runs once per launch, ~15us)
__global__ void convert_table(const float4* __restrict__ table4) {
    int i = blockIdx.x * blockDim.x + threadIdx.x;     // chunk index
    if (i >= TABLE_SIZE * 16) return;
    float4 v0 = __ldg(&table4[2 * i]);
    float4 v1 = __ldg(&table4[2 * i + 1]);
    uint4 w;
    w.x = pack_h2(v0.x, v0.y); w.y = pack_h2(v0.z, v0.w);
    w.z = pack_h2(v1.x, v1.y); w.w = pack_h2(v1.z, v1.w);
    g_tab16[i] = w;
}

// ---------------- helpers ----------------
__device__ __forceinline__ uint32_t smem_u32(const void* p) {
    uint32_t a;
    asm("{ .reg .u64 t; cvta.to.shared.u64 t, %1; cvt.u32.u64 %0, t; }" : "=r"(a) : "l"(p));
    return a;
}
// f16 tile swizzle: 256B rows, 16B chunk ^ (row&7)  (ldmatrix-compatible)
__device__ __forceinline__ uint32_t swz(int row, int chunk) {
    return (uint32_t)row * 256u + (uint32_t)(((chunk ^ (row & 7)) & 15) * 16);
}
// H swizzle: 256B f16 rows, 16B chunk ^ (row&15)
__device__ __forceinline__ uint32_t hswz(int row, int cc) {
    return (uint32_t)row * 256u + (uint32_t)(((cc ^ (row & 15)) & 15) * 16);
}
__device__ __forceinline__ void ldm_x4(uint32_t* a, uint32_t addr) {
    asm volatile("ldmatrix.sync.aligned.m8n8.x4.shared.b16 {%0,%1,%2,%3}, [%4];"
                 : "=r"(a[0]), "=r"(a[1]), "=r"(a[2]), "=r"(a[3]) : "r"(addr));
}
__device__ __forceinline__ void mma_f16(float* d, const uint32_t* a,
                                        uint32_t b0, uint32_t b1) {
    asm volatile(
        "mma.sync.aligned.m16n8k16.row.col.f32.f16.f16.f32 "
        "{%0,%1,%2,%3}, {%4,%5,%6,%7}, {%8,%9}, {%0,%1,%2,%3};"
        : "+f"(d[0]), "+f"(d[1]), "+f"(d[2]), "+f"(d[3])
        : "r"(a[0]), "r"(a[1]), "r"(a[2]), "r"(a[3]), "r"(b0), "r"(b1));
}
__device__ __forceinline__ float2 h2f2(uint32_t h) {
    float2 r;
    asm("{ .reg .b16 x, y; mov.b32 {x, y}, %2;"
        " cvt.f32.f16 %0, x; cvt.f32.f16 %1, y; }" : "=f"(r.x), "=f"(r.y) : "r"(h));
    return r;
}
__device__ __forceinline__ void cp16(uint32_t dst, const void* src) {
    asm volatile("cp.async.cg.shared.global [%0], [%1], 16;" :: "r"(dst), "l"(src) : "memory");
}

// gather a tile's 250 f16 rows straight into swizzled E via cp.async
__device__ __forceinline__ void prefetch_tile(
    uint32_t ebase, long long row_base, long long total_rows, int tid, int is64,
    const int* nb32, const long long* nb64)
{
    if (row_base < total_rows) {
        #pragma unroll
        for (int i = tid; i < ROWS_PER_TILE * 16; i += BLOCK_THREADS) {
            int r = i >> 4, c = i & 15;
            long long gr = row_base + r;
            long long nb = 0;
            if (gr < total_rows)
                nb = is64 ? __ldg(&nb64[gr]) : (long long)__ldg(&nb32[gr]);
            nb = nb < 0 ? 0 : (nb >= TABLE_SIZE ? TABLE_SIZE - 1 : nb);
            cp16(ebase + swz(r, c), g_tab16 + nb * 16 + c);
        }
    }
    asm volatile("cp.async.commit_group;" ::: "memory");
}

__global__ __launch_bounds__(BLOCK_THREADS, 1) void meanpool_kernel(
    const void* __restrict__ neighbors_raw,
    const float* __restrict__ W,
    const float* __restrict__ b,
    float* __restrict__ out,
    int n_nodes)
{
    extern __shared__ char s[];
    const uint32_t sbase = smem_u32(s);
    float* sB = (float*)(s + B_OFF);

    const int tid  = threadIdx.x;
    const int wid  = tid >> 5;
    const int lane = tid & 31;
    const int warp_m = wid & 3;      // 64-row block
    const int warp_n = wid >> 2;     // 32-col block
    const int is64 = g_idx_is64;

    // ---- Stage W (f16, swizzled) + bias; zero pad rows 250-255 of both E ----
    const float4* __restrict__ W4 = (const float4*)W;
    for (int i = tid; i < FDIM * 16; i += BLOCK_THREADS) {
        int f = i >> 4, c = i & 15;
        float4 v0 = __ldg(&W4[f * 32 + 2 * c]);
        float4 v1 = __ldg(&W4[f * 32 + 2 * c + 1]);
        uint4 w;
        w.x = pack_h2(v0.x, v0.y); w.y = pack_h2(v0.z, v0.w);
        w.z = pack_h2(v1.x, v1.y); w.w = pack_h2(v1.z, v1.w);
        *(uint4*)(s + W_OFF + swz(f, c)) = w;
    }
    if (tid < (M_PAD - ROWS_PER_TILE) * 16 * 2) {
        int buf = tid >= (M_PAD - ROWS_PER_TILE) * 16;
        int j = tid - buf * (M_PAD - ROWS_PER_TILE) * 16;
        int r = ROWS_PER_TILE + (j >> 4), c = j & 15;
        *(uint4*)(s + (buf ? E1_OFF : E0_OFF) + swz(r, c)) =
            make_uint4(0u, 0u, 0u, 0u);
    }
    if (tid < FDIM) sB[tid] = __ldg(&b[tid]);
    __syncthreads();

    // per-thread bias registers for the epilogue
    float bb[4][2];
    #pragma unroll
    for (int fn = 0; fn < 4; ++fn) {
        int c0 = warp_n * 32 + fn * 8 + (lane & 3) * 2;
        bb[fn][0] = sB[c0];
        bb[fn][1] = sB[c0 + 1];
    }

    const int* __restrict__       nb32 = (const int*)neighbors_raw;
    const long long* __restrict__ nb64 = (const long long*)neighbors_raw;

    const long long total_rows = (long long)n_nodes * S_SAMPLES;
    const int n_tiles = (int)((total_rows + ROWS_PER_TILE - 1) / ROWS_PER_TILE);

    // ---- prologue: prefetch tiles t0 -> E0, t1 -> E1 ----
    prefetch_tile(sbase + E0_OFF, (long long)blockIdx.x * ROWS_PER_TILE,
                  total_rows, tid, is64, nb32, nb64);
    prefetch_tile(sbase + E1_OFF, ((long long)blockIdx.x + GRID_BLOCKS) * ROWS_PER_TILE,
                  total_rows, tid, is64, nb32, nb64);

    // per-lane ldmatrix address components
    const int a_row = (lane & 15);
    const int a_kc  = lane >> 4;
    const int b_n   = (lane & 7);
    const int b_kc  = (lane >> 3) & 1;
    const int b_fs  = lane >> 4;

    int cur = 0;
    for (int tile = blockIdx.x; tile < n_tiles; tile += GRID_BLOCKS, cur ^= 1) {
        const uint32_t ebase = sbase + (cur ? E1_OFF : E0_OFF);

        // current tile's group done (one younger group may stay in flight)
        asm volatile("cp.async.wait_group 1;" ::: "memory");
        __syncthreads();

        // ---- single-term HMMA: 64x32 per warp ----
        float acc[4][4][4];
        #pragma unroll
        for (int fm = 0; fm < 4; ++fm)
            #pragma unroll
            for (int fn = 0; fn < 4; ++fn)
                #pragma unroll
                for (int j = 0; j < 4; ++j) acc[fm][fn][j] = 0.0f;

        #pragma unroll
        for (int ks = 0; ks < 8; ++ks) {
            uint32_t aF[4][4], bW[8];
            #pragma unroll
            for (int fm = 0; fm < 4; ++fm) {
                int row = warp_m * 64 + fm * 16 + a_row;
                ldm_x4(aF[fm], ebase + swz(row, ks * 2 + a_kc));
            }
            #pragma unroll
            for (int fp = 0; fp < 2; ++fp) {
                int n = warp_n * 32 + fp * 16 + b_fs * 8 + b_n;
                ldm_x4(bW + fp * 4, sbase + W_OFF + swz(n, ks * 2 + b_kc));
            }
            #pragma unroll
            for (int fm = 0; fm < 4; ++fm)
                #pragma unroll
                for (int fn = 0; fn < 4; ++fn)
                    mma_f16(acc[fm][fn], aF[fm], bW[fn * 2], bW[fn * 2 + 1]);
        }
        __syncthreads();   // all E reads done before H aliases this buffer

        // ---- bias+relu -> H (f16, aliases E[cur]) ----
        #pragma unroll
        for (int fm = 0; fm < 4; ++fm) {
            int r0 = warp_m * 64 + fm * 16 + (lane >> 2);
            #pragma unroll
            for (int fn = 0; fn < 4; ++fn) {
                int c0 = warp_n * 32 + fn * 8 + (lane & 3) * 2;
                int cc = c0 >> 3, byo = (c0 & 7) * 2;
                uint32_t h0 = pack_h2(fmaxf(acc[fm][fn][0] + bb[fn][0], 0.f),
                                      fmaxf(acc[fm][fn][1] + bb[fn][1], 0.f));
                uint32_t h1 = pack_h2(fmaxf(acc[fm][fn][2] + bb[fn][0], 0.f),
                                      fmaxf(acc[fm][fn][3] + bb[fn][1], 0.f));
                *(uint32_t*)(s + (ebase - sbase) + hswz(r0, cc) + byo)     = h0;
                *(uint32_t*)(s + (ebase - sbase) + hswz(r0 + 8, cc) + byo) = h1;
            }
        }
        __syncthreads();

        // ---- pool 25 rows per node (f16 H read, fp32 accumulate) ----
        const char* hb = s + (ebase - sbase);
        for (int i = tid; i < NODES_PER_TILE * 32; i += BLOCK_THREADS) {
            int g = i >> 5, cc2 = i & 31;          // 8B units within row
            float4 sum = make_float4(0.f, 0.f, 0.f, 0.f);
            #pragma unroll
            for (int ss = 0; ss < S_SAMPLES; ++ss) {
                int row = g * S_SAMPLES + ss;
                uint2 v = *(const uint2*)(hb + hswz(row, cc2 >> 1) + (cc2 & 1) * 8);
                float2 p0 = h2f2(v.x), p1 = h2f2(v.y);
                sum.x += p0.x; sum.y += p0.y; sum.z += p1.x; sum.w += p1.y;
            }
            long long n = (long long)tile * NODES_PER_TILE + g;
            if (n < n_nodes) {
                sum.x *= (1.0f / S_SAMPLES); sum.y *= (1.0f / S_SAMPLES);
                sum.z *= (1.0f / S_SAMPLES); sum.w *= (1.0f / S_SAMPLES);
                ((float4*)out)[n * 32 + cc2] = sum;
            }
        }
        __syncthreads();   // pool reads done before prefetch overwrites

        // ---- prefetch tile t+2 into this buffer ----
        prefetch_tile(ebase, ((long long)tile + 2 * GRID_BLOCKS) * ROWS_PER_TILE,
                      total_rows, tid, is64, nb32, nb64);

        // restore zero pad rows 250-255 (prefetch never writes them; H did)
        if (tid < (M_PAD - ROWS_PER_TILE) * 16) {
            int r = ROWS_PER_TILE + (tid >> 4), c = tid & 15;
            *(uint4*)(s + (ebase - sbase) + swz(r, c)) = make_uint4(0u, 0u, 0u, 0u);
        }
    }
}

extern "C" void kernel_launch(void* const* d_in, const int* in_sizes, int n_in,
                              void* d_out, int out_size) {
    const void*  neighbors = d_in[0];
    const float* emb_table = (const float*)d_in[1];
    const float* W         = (const float*)d_in[2];
    const float* b         = (const float*)d_in[3];
    float*       out       = (float*)d_out;

    const int n_nodes = in_sizes[0] / S_SAMPLES;

    cudaFuncSetAttribute(meanpool_kernel,
                         cudaFuncAttributeMaxDynamicSharedMemorySize, SMEM_TOTAL);

    detect_idx_dtype<<<1, 1>>>((const int*)neighbors);
    convert_table<<<(TABLE_SIZE * 16 + 255) / 256, 256>>>((const float4*)emb_table);
    meanpool_kernel<<<GRID_BLOCKS, BLOCK_THREADS, SMEM_TOTAL>>>(
        neighbors, W, b, out, n_nodes);
}

// round 10
// speedup vs baseline: 8.5050x; 1.3389x over previous
#include <cuda_runtime.h>
#include <cuda_fp16.h>
#include <cstdint>

// out[n,f] = (1/25) * sum_s relu( dot(E[nbr[n,s],:], W[f,:]) + b[f] )
// f16 HMMA (fp32 accum), table pre-converted to a __device__ f16 mirror once.
// Gather cp.asyncs f16 chunks directly into swizzled double-buffered E tiles.
// M=128 tiles (5 nodes), 256 thr = 8 warps (2m x 4n), 2 CTAs/SM so one CTA's
// MMA overlaps the other's epilogue/pool. H (f16) aliases the consumed E.

#define S_SAMPLES 25
#define FDIM 128
#define TABLE_SIZE 100000
#define ROWS_PER_TILE 125
#define NODES_PER_TILE 5
#define M_PAD 128
#define BLOCK_THREADS 256
#define GRID_BLOCKS 296            // 2 per SM

#define E0_OFF 0                   // [128][256B] f16, swizzled (double buffer)
#define E1_OFF 32768
#define W_OFF  65536               // [128][256B] f16, swizzled
#define B_OFF  98304               // bias 512B
#define SMEM_TOTAL 98944

__device__ int g_idx_is64;
__device__ uint4 g_tab16[TABLE_SIZE * 16];   // f16 table mirror, 16B chunks

__device__ __forceinline__ uint32_t pack_h2(float a, float b) {
    uint32_t r;
    asm("{ .reg .b16 x, y; cvt.rn.f16.f32 x, %1; cvt.rn.f16.f32 y, %2;"
        " mov.b32 %0, {x, y}; }" : "=r"(r) : "f"(a), "f"(b));
    return r;
}

// fp32 table -> f16 mirror; block 0 thread 0 also detects the index dtype.
__global__ void convert_table(const float4* __restrict__ table4,
                              const int* __restrict__ nb32) {
    if (blockIdx.x == 0 && threadIdx.x == 0) {
        // int64 LE: hi word of every value <100000 is 0; int32: odd words random.
        int is64 = 1;
        #pragma unroll
        for (int i = 1; i < 64; i += 2) if (nb32[i] != 0) is64 = 0;
        g_idx_is64 = is64;
    }
    int i = blockIdx.x * blockDim.x + threadIdx.x;     // 16B chunk index
    if (i >= TABLE_SIZE * 16) return;
    float4 v0 = __ldg(&table4[2 * i]);
    float4 v1 = __ldg(&table4[2 * i + 1]);
    uint4 w;
    w.x = pack_h2(v0.x, v0.y); w.y = pack_h2(v0.z, v0.w);
    w.z = pack_h2(v1.x, v1.y); w.w = pack_h2(v1.z, v1.w);
    g_tab16[i] = w;
}

// ---------------- helpers ----------------
__device__ __forceinline__ uint32_t smem_u32(const void* p) {
    uint32_t a;
    asm("{ .reg .u64 t; cvta.to.shared.u64 t, %1; cvt.u32.u64 %0, t; }" : "=r"(a) : "l"(p));
    return a;
}
// f16 tile swizzle: 256B rows, 16B chunk ^ (row&7)  (ldmatrix-compatible)
__device__ __forceinline__ uint32_t swz(int row, int chunk) {
    return (uint32_t)row * 256u + (uint32_t)(((chunk ^ (row & 7)) & 15) * 16);
}
// H swizzle: 256B f16 rows, 16B chunk ^ (row&15)
__device__ __forceinline__ uint32_t hswz(int row, int cc) {
    return (uint32_t)row * 256u + (uint32_t)(((cc ^ (row & 15)) & 15) * 16);
}
__device__ __forceinline__ void ldm_x4(uint32_t* a, uint32_t addr) {
    asm volatile("ldmatrix.sync.aligned.m8n8.x4.shared.b16 {%0,%1,%2,%3}, [%4];"
                 : "=r"(a[0]), "=r"(a[1]), "=r"(a[2]), "=r"(a[3]) : "r"(addr));
}
__device__ __forceinline__ void mma_f16(float* d, const uint32_t* a,
                                        uint32_t b0, uint32_t b1) {
    asm volatile(
        "mma.sync.aligned.m16n8k16.row.col.f32.f16.f16.f32 "
        "{%0,%1,%2,%3}, {%4,%5,%6,%7}, {%8,%9}, {%0,%1,%2,%3};"
        : "+f"(d[0]), "+f"(d[1]), "+f"(d[2]), "+f"(d[3])
        : "r"(a[0]), "r"(a[1]), "r"(a[2]), "r"(a[3]), "r"(b0), "r"(b1));
}
__device__ __forceinline__ float2 h2f2(uint32_t h) {
    float2 r;
    asm("{ .reg .b16 x, y; mov.b32 {x, y}, %2;"
        " cvt.f32.f16 %0, x; cvt.f32.f16 %1, y; }" : "=f"(r.x), "=f"(r.y) : "r"(h));
    return r;
}
__device__ __forceinline__ void cp16(uint32_t dst, const void* src) {
    asm volatile("cp.async.cg.shared.global [%0], [%1], 16;" :: "r"(dst), "l"(src) : "memory");
}

// gather a tile's 125 f16 rows straight into swizzled E via cp.async
__device__ __forceinline__ void prefetch_tile(
    uint32_t ebase, long long row_base, long long total_rows, int tid, int is64,
    const int* nb32, const long long* nb64)
{
    if (row_base < total_rows) {
        #pragma unroll
        for (int i = tid; i < ROWS_PER_TILE * 16; i += BLOCK_THREADS) {
            int r = i >> 4, c = i & 15;
            long long gr = row_base + r;
            long long nb = 0;
            if (gr < total_rows)
                nb = is64 ? __ldg(&nb64[gr]) : (long long)__ldg(&nb32[gr]);
            nb = nb < 0 ? 0 : (nb >= TABLE_SIZE ? TABLE_SIZE - 1 : nb);
            cp16(ebase + swz(r, c), g_tab16 + nb * 16 + c);
        }
    }
    asm volatile("cp.async.commit_group;" ::: "memory");
}

__global__ __launch_bounds__(BLOCK_THREADS, 2) void meanpool_kernel(
    const void* __restrict__ neighbors_raw,
    const float* __restrict__ W,
    const float* __restrict__ b,
    float* __restrict__ out,
    int n_nodes)
{
    extern __shared__ char s[];
    const uint32_t sbase = smem_u32(s);
    float* sB = (float*)(s + B_OFF);

    const int tid  = threadIdx.x;
    const int wid  = tid >> 5;
    const int lane = tid & 31;
    const int warp_m = wid & 1;      // 64-row block
    const int warp_n = wid >> 1;     // 32-col block
    const int is64 = g_idx_is64;

    // ---- Stage W (f16, swizzled) + bias; zero pad rows 125-127 of both E ----
    const float4* __restrict__ W4 = (const float4*)W;
    for (int i = tid; i < FDIM * 16; i += BLOCK_THREADS) {
        int f = i >> 4, c = i & 15;
        float4 v0 = __ldg(&W4[f * 32 + 2 * c]);
        float4 v1 = __ldg(&W4[f * 32 + 2 * c + 1]);
        uint4 w;
        w.x = pack_h2(v0.x, v0.y); w.y = pack_h2(v0.z, v0.w);
        w.z = pack_h2(v1.x, v1.y); w.w = pack_h2(v1.z, v1.w);
        *(uint4*)(s + W_OFF + swz(f, c)) = w;
    }
    if (tid < (M_PAD - ROWS_PER_TILE) * 16 * 2) {   // 96 threads
        int buf = tid >= (M_PAD - ROWS_PER_TILE) * 16;
        int j = tid - buf * (M_PAD - ROWS_PER_TILE) * 16;
        int r = ROWS_PER_TILE + (j >> 4), c = j & 15;
        *(uint4*)(s + (buf ? E1_OFF : E0_OFF) + swz(r, c)) = make_uint4(0u, 0u, 0u, 0u);
    }
    if (tid < FDIM) sB[tid] = __ldg(&b[tid]);
    __syncthreads();

    // per-thread bias registers for the epilogue
    float bb[4][2];
    #pragma unroll
    for (int fn = 0; fn < 4; ++fn) {
        int c0 = warp_n * 32 + fn * 8 + (lane & 3) * 2;
        bb[fn][0] = sB[c0];
        bb[fn][1] = sB[c0 + 1];
    }

    const int* __restrict__       nb32 = (const int*)neighbors_raw;
    const long long* __restrict__ nb64 = (const long long*)neighbors_raw;

    const long long total_rows = (long long)n_nodes * S_SAMPLES;
    const int n_tiles = (int)((total_rows + ROWS_PER_TILE - 1) / ROWS_PER_TILE);

    // ---- prologue: prefetch tiles t0 -> E0, t1 -> E1 ----
    prefetch_tile(sbase + E0_OFF, (long long)blockIdx.x * ROWS_PER_TILE,
                  total_rows, tid, is64, nb32, nb64);
    prefetch_tile(sbase + E1_OFF, ((long long)blockIdx.x + GRID_BLOCKS) * ROWS_PER_TILE,
                  total_rows, tid, is64, nb32, nb64);

    // per-lane ldmatrix address components
    const int a_row = (lane & 15);
    const int a_kc  = lane >> 4;
    const int b_n   = (lane & 7);
    const int b_kc  = (lane >> 3) & 1;
    const int b_fs  = lane >> 4;

    int cur = 0;
    for (int tile = blockIdx.x; tile < n_tiles; tile += GRID_BLOCKS, cur ^= 1) {
        const uint32_t ebase = sbase + (cur ? E1_OFF : E0_OFF);
        const char*    hb    = s + (cur ? E1_OFF : E0_OFF);

        // current tile's cp.async group done (one younger group in flight)
        asm volatile("cp.async.wait_group 1;" ::: "memory");
        __syncthreads();

        // ---- single-term HMMA: 64x32 per warp ----
        float acc[4][4][4];
        #pragma unroll
        for (int fm = 0; fm < 4; ++fm)
            #pragma unroll
            for (int fn = 0; fn < 4; ++fn)
                #pragma unroll
                for (int j = 0; j < 4; ++j) acc[fm][fn][j] = 0.0f;

        #pragma unroll
        for (int ks = 0; ks < 8; ++ks) {
            uint32_t aF[4][4], bW[8];
            #pragma unroll
            for (int fm = 0; fm < 4; ++fm) {
                int row = warp_m * 64 + fm * 16 + a_row;
                ldm_x4(aF[fm], ebase + swz(row, ks * 2 + a_kc));
            }
            #pragma unroll
            for (int fp = 0; fp < 2; ++fp) {
                int n = warp_n * 32 + fp * 16 + b_fs * 8 + b_n;
                ldm_x4(bW + fp * 4, sbase + W_OFF + swz(n, ks * 2 + b_kc));
            }
            #pragma unroll
            for (int fm = 0; fm < 4; ++fm)
                #pragma unroll
                for (int fn = 0; fn < 4; ++fn)
                    mma_f16(acc[fm][fn], aF[fm], bW[fn * 2], bW[fn * 2 + 1]);
        }
        __syncthreads();   // all E reads done before H aliases this buffer

        // ---- bias+relu -> H (f16, aliases E[cur]) ----
        #pragma unroll
        for (int fm = 0; fm < 4; ++fm) {
            int r0 = warp_m * 64 + fm * 16 + (lane >> 2);
            #pragma unroll
            for (int fn = 0; fn < 4; ++fn) {
                int c0 = warp_n * 32 + fn * 8 + (lane & 3) * 2;
                int cc = c0 >> 3, byo = (c0 & 7) * 2;
                uint32_t h0 = pack_h2(fmaxf(acc[fm][fn][0] + bb[fn][0], 0.f),
                                      fmaxf(acc[fm][fn][1] + bb[fn][1], 0.f));
                uint32_t h1 = pack_h2(fmaxf(acc[fm][fn][2] + bb[fn][0], 0.f),
                                      fmaxf(acc[fm][fn][3] + bb[fn][1], 0.f));
                *(uint32_t*)(hb + hswz(r0, cc) + byo)     = h0;
                *(uint32_t*)(hb + hswz(r0 + 8, cc) + byo) = h1;
            }
        }
        __syncthreads();

        // ---- pool 25 rows per node (f16 H read, fp32 accumulate) ----
        for (int i = tid; i < NODES_PER_TILE * 32; i += BLOCK_THREADS) {
            int g = i >> 5, cc2 = i & 31;          // 8B units within row
            float4 sum = make_float4(0.f, 0.f, 0.f, 0.f);
            #pragma unroll
            for (int ss = 0; ss < S_SAMPLES; ++ss) {
                int row = g * S_SAMPLES + ss;
                uint2 v = *(const uint2*)(hb + hswz(row, cc2 >> 1) + (cc2 & 1) * 8);
                float2 p0 = h2f2(v.x), p1 = h2f2(v.y);
                sum.x += p0.x; sum.y += p0.y; sum.z += p1.x; sum.w += p1.y;
            }
            long long n = (long long)tile * NODES_PER_TILE + g;
            if (n < n_nodes) {
                sum.x *= (1.0f / S_SAMPLES); sum.y *= (1.0f / S_SAMPLES);
                sum.z *= (1.0f / S_SAMPLES); sum.w *= (1.0f / S_SAMPLES);
                ((float4*)out)[n * 32 + cc2] = sum;
            }
        }
        __syncthreads();   // pool reads done before prefetch overwrites

        // ---- prefetch tile t+2 into this buffer ----
        prefetch_tile(ebase, ((long long)tile + 2 * GRID_BLOCKS) * ROWS_PER_TILE,
                      total_rows, tid, is64, nb32, nb64);

        // restore zero pad rows 125-127 (H wrote them; prefetch doesn't)
        if (tid < (M_PAD - ROWS_PER_TILE) * 16) {
            int r = ROWS_PER_TILE + (tid >> 4), c = tid & 15;
            *(uint4*)(hb + swz(r, c)) = make_uint4(0u, 0u, 0u, 0u);
        }
    }
}

extern "C" void kernel_launch(void* const* d_in, const int* in_sizes, int n_in,
                              void* d_out, int out_size) {
    const void*  neighbors = d_in[0];
    const float* emb_table = (const float*)d_in[1];
    const float* W         = (const float*)d_in[2];
    const float* b         = (const float*)d_in[3];
    float*       out       = (float*)d_out;

    const int n_nodes = in_sizes[0] / S_SAMPLES;

    cudaFuncSetAttribute(meanpool_kernel,
                         cudaFuncAttributeMaxDynamicSharedMemorySize, SMEM_TOTAL);

    convert_table<<<(TABLE_SIZE * 16 + 255) / 256, 256>>>((const float4*)emb_table,
                                                          (const int*)neighbors);
    meanpool_kernel<<<GRID_BLOCKS, BLOCK_THREADS, SMEM_TOTAL>>>(
        neighbors, W, b, out, n_nodes);
}

// round 11
// speedup vs baseline: 10.0563x; 1.1824x over previous
#include <cuda_runtime.h>
#include <cuda_fp16.h>
#include <cstdint>

// out[n,f] = (1/25) * sum_s relu( dot(E[nbr[n,s],:], W[f,:]) + b[f] )
// f16 HMMA (fp32 accum); table pre-converted to a __device__ f16 mirror.
// Gather cp.asyncs f16 chunks directly into swizzled double-buffered E tiles.
// M=128 tiles (5 nodes), 256 thr = 8 warps (2m x 4n), 2 CTAs/SM.
// H (f16) aliases the consumed E; mean-pool is a second MMA against a
// constant block-ones matrix P (A-fragments precomputed in smem).

#define S_SAMPLES 25
#define FDIM 128
#define TABLE_SIZE 100000
#define ROWS_PER_TILE 125
#define NODES_PER_TILE 5
#define M_PAD 128
#define BLOCK_THREADS 256
#define GRID_BLOCKS 296            // 2 per SM

#define E0_OFF 0                   // [128][256B] f16, swizzled (double buffer)
#define E1_OFF 32768
#define W_OFF  65536               // [128][256B] f16, swizzled
#define B_OFF  98304               // bias 512B
#define P_OFF  98816               // pool A-fragments: 8 kc x 32 lanes x 16B = 4KB
#define SMEM_TOTAL 102912

__device__ int g_idx_is64;
__device__ uint4 g_tab16[TABLE_SIZE * 16];   // f16 table mirror, 16B chunks

__device__ __forceinline__ uint32_t pack_h2(float a, float b) {
    uint32_t r;
    asm("{ .reg .b16 x, y; cvt.rn.f16.f32 x, %1; cvt.rn.f16.f32 y, %2;"
        " mov.b32 %0, {x, y}; }" : "=r"(r) : "f"(a), "f"(b));
    return r;
}

// fp32 table -> f16 mirror; block 0 thread 0 also detects the index dtype.
__global__ void convert_table(const float4* __restrict__ table4,
                              const int* __restrict__ nb32) {
    if (blockIdx.x == 0 && threadIdx.x == 0) {
        int is64 = 1;
        #pragma unroll
        for (int i = 1; i < 64; i += 2) if (nb32[i] != 0) is64 = 0;
        g_idx_is64 = is64;
    }
    int i = blockIdx.x * blockDim.x + threadIdx.x;     // 16B chunk index
    if (i >= TABLE_SIZE * 16) return;
    float4 v0 = __ldg(&table4[2 * i]);
    float4 v1 = __ldg(&table4[2 * i + 1]);
    uint4 w;
    w.x = pack_h2(v0.x, v0.y); w.y = pack_h2(v0.z, v0.w);
    w.z = pack_h2(v1.x, v1.y); w.w = pack_h2(v1.z, v1.w);
    g_tab16[i] = w;
}

// ---------------- helpers ----------------
__device__ __forceinline__ uint32_t smem_u32(const void* p) {
    uint32_t a;
    asm("{ .reg .u64 t; cvta.to.shared.u64 t, %1; cvt.u32.u64 %0, t; }" : "=r"(a) : "l"(p));
    return a;
}
// f16 tile swizzle: 256B rows, 16B chunk ^ (row&7)  (ldmatrix-compatible)
__device__ __forceinline__ uint32_t swz(int row, int chunk) {
    return (uint32_t)row * 256u + (uint32_t)(((chunk ^ (row & 7)) & 15) * 16);
}
// H swizzle: 256B f16 rows, 16B chunk ^ (row&15)
__device__ __forceinline__ uint32_t hswz(int row, int cc) {
    return (uint32_t)row * 256u + (uint32_t)(((cc ^ (row & 15)) & 15) * 16);
}
__device__ __forceinline__ void ldm_x4(uint32_t* a, uint32_t addr) {
    asm volatile("ldmatrix.sync.aligned.m8n8.x4.shared.b16 {%0,%1,%2,%3}, [%4];"
                 : "=r"(a[0]), "=r"(a[1]), "=r"(a[2]), "=r"(a[3]) : "r"(addr));
}
__device__ __forceinline__ void ldm_x4_t(uint32_t* a, uint32_t addr) {
    asm volatile("ldmatrix.sync.aligned.m8n8.x4.trans.shared.b16 {%0,%1,%2,%3}, [%4];"
                 : "=r"(a[0]), "=r"(a[1]), "=r"(a[2]), "=r"(a[3]) : "r"(addr));
}
__device__ __forceinline__ void mma_f16(float* d, const uint32_t* a,
                                        uint32_t b0, uint32_t b1) {
    asm volatile(
        "mma.sync.aligned.m16n8k16.row.col.f32.f16.f16.f32 "
        "{%0,%1,%2,%3}, {%4,%5,%6,%7}, {%8,%9}, {%0,%1,%2,%3};"
        : "+f"(d[0]), "+f"(d[1]), "+f"(d[2]), "+f"(d[3])
        : "r"(a[0]), "r"(a[1]), "r"(a[2]), "r"(a[3]), "r"(b0), "r"(b1));
}
__device__ __forceinline__ void cp16(uint32_t dst, const void* src) {
    asm volatile("cp.async.cg.shared.global [%0], [%1], 16;" :: "r"(dst), "l"(src) : "memory");
}

// gather a tile's 125 f16 rows straight into swizzled E via cp.async.
// per-thread: column chunk c and (r&7) are loop-invariant (row stride 16).
__device__ __forceinline__ void prefetch_tile(
    uint32_t ebase, long long row_base, long long total_rows, int tid, int is64,
    const int* nb32, const long long* nb64)
{
    if (row_base < total_rows) {
        const int r0 = tid >> 4, c = tid & 15;
        const uint32_t dst0 = ebase + (uint32_t)r0 * 256u +
                              (uint32_t)(((c ^ (r0 & 7)) & 15) * 16);
        const char* src0 = (const char*)g_tab16 + c * 16;
        #pragma unroll
        for (int j = 0; j < 8; ++j) {
            int r = r0 + j * 16;
            if (r < ROWS_PER_TILE) {
                long long gr = row_base + r;
                long long nb = is64 ? __ldg(&nb64[gr]) : (long long)__ldg(&nb32[gr]);
                nb = nb < 0 ? 0 : (nb >= TABLE_SIZE ? TABLE_SIZE - 1 : nb);
                cp16(dst0 + (uint32_t)j * 4096u, src0 + nb * 256);
            }
        }
    }
    asm volatile("cp.async.commit_group;" ::: "memory");
}

__global__ __launch_bounds__(BLOCK_THREADS, 2) void meanpool_kernel(
    const void* __restrict__ neighbors_raw,
    const float* __restrict__ W,
    const float* __restrict__ b,
    float* __restrict__ out,
    int n_nodes)
{
    extern __shared__ char s[];
    const uint32_t sbase = smem_u32(s);
    float* sB = (float*)(s + B_OFF);

    const int tid  = threadIdx.x;
    const int wid  = tid >> 5;
    const int lane = tid & 31;
    const int warp_m = wid & 1;      // 64-row block
    const int warp_n = wid >> 1;     // 32-col block
    const int is64 = g_idx_is64;

    // ---- Stage W (f16, swizzled) + bias; zero pad rows (keep pads finite) ----
    const float4* __restrict__ W4 = (const float4*)W;
    for (int i = tid; i < FDIM * 16; i += BLOCK_THREADS) {
        int f = i >> 4, c = i & 15;
        float4 v0 = __ldg(&W4[f * 32 + 2 * c]);
        float4 v1 = __ldg(&W4[f * 32 + 2 * c + 1]);
        uint4 w;
        w.x = pack_h2(v0.x, v0.y); w.y = pack_h2(v0.z, v0.w);
        w.z = pack_h2(v1.x, v1.y); w.w = pack_h2(v1.z, v1.w);
        *(uint4*)(s + W_OFF + swz(f, c)) = w;
    }
    if (tid < (M_PAD - ROWS_PER_TILE) * 16 * 2) {   // 96 threads, once
        int buf = tid >= (M_PAD - ROWS_PER_TILE) * 16;
        int j = tid - buf * (M_PAD - ROWS_PER_TILE) * 16;
        int r = ROWS_PER_TILE + (j >> 4), c = j & 15;
        *(uint4*)(s + (buf ? E1_OFF : E0_OFF) + swz(r, c)) = make_uint4(0u, 0u, 0u, 0u);
    }
    if (tid < FDIM) sB[tid] = __ldg(&b[tid]);

    // ---- Build pool A-fragments P[16x128] (block-ones), m16n8k16 A layout ----
    // entry tid = kc*32 + lane; regs a0..a3 rows {r,r+8,r,r+8}, k offs {0,0,8,8}
    {
        int kc = tid >> 5, ln = tid & 31;
        int r = ln >> 2, kb = kc * 16 + (ln & 3) * 2;
        uint4 pf;
        uint32_t* pp = (uint32_t*)&pf;
        #pragma unroll
        for (int j = 0; j < 4; ++j) {
            int row = r + ((j & 1) << 3);
            int k = kb + ((j >> 1) << 3);
            float v0 = (row < NODES_PER_TILE && k >= 25 * row && k < 25 * row + 25) ? 1.f : 0.f;
            float v1 = (row < NODES_PER_TILE && k + 1 >= 25 * row && k + 1 < 25 * row + 25) ? 1.f : 0.f;
            pp[j] = pack_h2(v0, v1);
        }
        *(uint4*)(s + P_OFF + tid * 16) = pf;
    }
    __syncthreads();

    // per-thread bias registers for the epilogue
    float bb[4][2];
    #pragma unroll
    for (int fn = 0; fn < 4; ++fn) {
        int c0 = warp_n * 32 + fn * 8 + (lane & 3) * 2;
        bb[fn][0] = sB[c0];
        bb[fn][1] = sB[c0 + 1];
    }

    const int* __restrict__       nb32 = (const int*)neighbors_raw;
    const long long* __restrict__ nb64 = (const long long*)neighbors_raw;

    const long long total_rows = (long long)n_nodes * S_SAMPLES;
    const int n_tiles = (int)((total_rows + ROWS_PER_TILE - 1) / ROWS_PER_TILE);

    // ---- prologue: prefetch tiles t0 -> E0, t1 -> E1 ----
    prefetch_tile(sbase + E0_OFF, (long long)blockIdx.x * ROWS_PER_TILE,
                  total_rows, tid, is64, nb32, nb64);
    prefetch_tile(sbase + E1_OFF, ((long long)blockIdx.x + GRID_BLOCKS) * ROWS_PER_TILE,
                  total_rows, tid, is64, nb32, nb64);

    // per-lane ldmatrix address components (main MMA)
    const int a_row = (lane & 15);
    const int a_kc  = lane >> 4;
    const int b_n   = (lane & 7);
    const int b_kc  = (lane >> 3) & 1;
    const int b_fs  = lane >> 4;
    // pool ldmatrix components: parts {k0f0, k8f0, k0f8, k8f8}
    const int p_row = ((lane >> 3) & 1) * 8 + (lane & 7);
    const int p_cc  = ((wid * 16) + ((lane >> 4) << 3)) >> 3;

    int cur = 0;
    for (int tile = blockIdx.x; tile < n_tiles; tile += GRID_BLOCKS, cur ^= 1) {
        const uint32_t ebase = sbase + (cur ? E1_OFF : E0_OFF);
        const char*    hb    = s + (cur ? E1_OFF : E0_OFF);

        // current tile's cp.async group done (one younger group in flight)
        asm volatile("cp.async.wait_group 1;" ::: "memory");
        __syncthreads();

        // ---- main HMMA: 64x32 per warp ----
        float acc[4][4][4];
        #pragma unroll
        for (int fm = 0; fm < 4; ++fm)
            #pragma unroll
            for (int fn = 0; fn < 4; ++fn)
                #pragma unroll
                for (int j = 0; j < 4; ++j) acc[fm][fn][j] = 0.0f;

        #pragma unroll
        for (int ks = 0; ks < 8; ++ks) {
            uint32_t aF[4][4], bW[8];
            #pragma unroll
            for (int fm = 0; fm < 4; ++fm) {
                int row = warp_m * 64 + fm * 16 + a_row;
                ldm_x4(aF[fm], ebase + swz(row, ks * 2 + a_kc));
            }
            #pragma unroll
            for (int fp = 0; fp < 2; ++fp) {
                int n = warp_n * 32 + fp * 16 + b_fs * 8 + b_n;
                ldm_x4(bW + fp * 4, sbase + W_OFF + swz(n, ks * 2 + b_kc));
            }
            #pragma unroll
            for (int fm = 0; fm < 4; ++fm)
                #pragma unroll
                for (int fn = 0; fn < 4; ++fn)
                    mma_f16(acc[fm][fn], aF[fm], bW[fn * 2], bW[fn * 2 + 1]);
        }
        __syncthreads();   // all E reads done before H aliases this buffer

        // ---- bias+relu -> H (f16, aliases E[cur]; pads get finite garbage) ----
        #pragma unroll
        for (int fm = 0; fm < 4; ++fm) {
            int r0 = warp_m * 64 + fm * 16 + (lane >> 2);
            #pragma unroll
            for (int fn = 0; fn < 4; ++fn) {
                int c0 = warp_n * 32 + fn * 8 + (lane & 3) * 2;
                int cc = c0 >> 3, byo = (c0 & 7) * 2;
                uint32_t h0 = pack_h2(fmaxf(acc[fm][fn][0] + bb[fn][0], 0.f),
                                      fmaxf(acc[fm][fn][1] + bb[fn][1], 0.f));
                uint32_t h1 = pack_h2(fmaxf(acc[fm][fn][2] + bb[fn][0], 0.f),
                                      fmaxf(acc[fm][fn][3] + bb[fn][1], 0.f));
                *(uint32_t*)(hb + hswz(r0, cc) + byo)     = h0;
                *(uint32_t*)(hb + hswz(r0 + 8, cc) + byo) = h1;
            }
        }
        __syncthreads();

        // ---- pool MMA: D[5x16 per warp] = P @ H (P zeros kill pad rows) ----
        {
            float dp0[4] = {0.f, 0.f, 0.f, 0.f}, dp1[4] = {0.f, 0.f, 0.f, 0.f};
            #pragma unroll
            for (int kc = 0; kc < 8; ++kc) {
                uint32_t pf[4], bf[4];
                *(uint4*)pf = *(const uint4*)(s + P_OFF + ((kc << 5) + lane) * 16);
                ldm_x4_t(bf, ebase + hswz(kc * 16 + p_row, p_cc));
                mma_f16(dp0, pf, bf[0], bf[1]);
                mma_f16(dp1, pf, bf[2], bf[3]);
            }
            int g = lane >> 2;
            if (g < NODES_PER_TILE) {
                long long n = (long long)tile * NODES_PER_TILE + g;
                if (n < n_nodes) {
                    const float sc = 1.0f / (float)S_SAMPLES;
                    int cb = wid * 16 + (lane & 3) * 2;
                    *(float2*)&out[n * FDIM + cb]     = make_float2(dp0[0] * sc, dp0[1] * sc);
                    *(float2*)&out[n * FDIM + cb + 8] = make_float2(dp1[0] * sc, dp1[1] * sc);
                }
            }
        }
        __syncthreads();   // pool reads done before prefetch overwrites

        // ---- prefetch tile t+2 into this buffer ----
        prefetch_tile(ebase, ((long long)tile + 2 * GRID_BLOCKS) * ROWS_PER_TILE,
                      total_rows, tid, is64, nb32, nb64);
    }
}

extern "C" void kernel_launch(void* const* d_in, const int* in_sizes, int n_in,
                              void* d_out, int out_size) {
    const void*  neighbors = d_in[0];
    const float* emb_table = (const float*)d_in[1];
    const float* W         = (const float*)d_in[2];
    const float* b         = (const float*)d_in[3];
    float*       out       = (float*)d_out;

    const int n_nodes = in_sizes[0] / S_SAMPLES;

    cudaFuncSetAttribute(meanpool_kernel,
                         cudaFuncAttributeMaxDynamicSharedMemorySize, SMEM_TOTAL);

    convert_table<<<(TABLE_SIZE * 16 + 255) / 256, 256>>>((const float4*)emb_table,
                                                          (const int*)neighbors);
    meanpool_kernel<<<GRID_BLOCKS, BLOCK_THREADS, SMEM_TOTAL>>>(
        neighbors, W, b, out, n_nodes);
}

// round 12
// speedup vs baseline: 11.2322x; 1.1169x over previous
#include <cuda_runtime.h>
#include <cuda_fp16.h>
#include <cstdint>

// out[n,f] = (1/25) * sum_s relu( dot(E[nbr[n,s],:], W[f,:]) + b[f] )
// f16 HMMA (fp32 accum); table pre-converted to a __device__ f16 mirror.
// Gather: ONE cp.async.bulk (256B) per embedding row into a 272B-stride
// (pad-swizzled) E tile, completion via mbarrier expect_tx/complete_tx.
// M=128 tiles (5 nodes), 256 thr = 8 warps (2m x 4n), 2 CTAs/SM.
// H (f16) aliases consumed E; mean-pool = MMA against block-ones P.

#define S_SAMPLES 25
#define FDIM 128
#define TABLE_SIZE 100000
#define ROWS_PER_TILE 125
#define NODES_PER_TILE 5
#define M_PAD 128
#define BLOCK_THREADS 256
#define GRID_BLOCKS 296            // 2 per SM

#define ROW_STRIDE 272             // 256B data + 16B pad -> conflict-free ldmatrix
#define TILE_BYTES (M_PAD * ROW_STRIDE)   // 34816

#define E0_OFF 0
#define E1_OFF TILE_BYTES          // 34816
#define W_OFF  (2 * TILE_BYTES)    // 69632
#define B_OFF  (3 * TILE_BYTES)    // 104448 (bias 512B)
#define P_OFF  (B_OFF + 512)       // 104960 (pool A-frags 4KB)
#define MBAR_OFF (P_OFF + 4096)    // 109056 (2 x 8B)
#define SMEM_TOTAL (MBAR_OFF + 32)

__device__ int g_idx_is64;
__device__ uint4 g_tab16[TABLE_SIZE * 16];   // f16 table mirror, 256B rows

__device__ __forceinline__ uint32_t pack_h2(float a, float b) {
    uint32_t r;
    asm("{ .reg .b16 x, y; cvt.rn.f16.f32 x, %1; cvt.rn.f16.f32 y, %2;"
        " mov.b32 %0, {x, y}; }" : "=r"(r) : "f"(a), "f"(b));
    return r;
}

// fp32 table -> f16 mirror; block 0 thread 0 also detects the index dtype.
__global__ void convert_table(const float4* __restrict__ table4,
                              const int* __restrict__ nb32) {
    if (blockIdx.x == 0 && threadIdx.x == 0) {
        int is64 = 1;
        #pragma unroll
        for (int i = 1; i < 64; i += 2) if (nb32[i] != 0) is64 = 0;
        g_idx_is64 = is64;
    }
    int i = blockIdx.x * blockDim.x + threadIdx.x;     // 16B chunk index
    if (i >= TABLE_SIZE * 16) return;
    float4 v0 = __ldg(&table4[2 * i]);
    float4 v1 = __ldg(&table4[2 * i + 1]);
    uint4 w;
    w.x = pack_h2(v0.x, v0.y); w.y = pack_h2(v0.z, v0.w);
    w.z = pack_h2(v1.x, v1.y); w.w = pack_h2(v1.z, v1.w);
    g_tab16[i] = w;
}

// ---------------- helpers ----------------
__device__ __forceinline__ uint32_t smem_u32(const void* p) {
    uint32_t a;
    asm("{ .reg .u64 t; cvta.to.shared.u64 t, %1; cvt.u32.u64 %0, t; }" : "=r"(a) : "l"(p));
    return a;
}
// padded-stride addressing (replaces XOR swizzle; chunk in 16B units)
__device__ __forceinline__ uint32_t ew(int row, int chunk) {
    return (uint32_t)row * ROW_STRIDE + (uint32_t)chunk * 16u;
}
__device__ __forceinline__ void ldm_x4(uint32_t* a, uint32_t addr) {
    asm volatile("ldmatrix.sync.aligned.m8n8.x4.shared.b16 {%0,%1,%2,%3}, [%4];"
                 : "=r"(a[0]), "=r"(a[1]), "=r"(a[2]), "=r"(a[3]) : "r"(addr));
}
__device__ __forceinline__ void ldm_x4_t(uint32_t* a, uint32_t addr) {
    asm volatile("ldmatrix.sync.aligned.m8n8.x4.trans.shared.b16 {%0,%1,%2,%3}, [%4];"
                 : "=r"(a[0]), "=r"(a[1]), "=r"(a[2]), "=r"(a[3]) : "r"(addr));
}
__device__ __forceinline__ void mma_f16(float* d, const uint32_t* a,
                                        uint32_t b0, uint32_t b1) {
    asm volatile(
        "mma.sync.aligned.m16n8k16.row.col.f32.f16.f16.f32 "
        "{%0,%1,%2,%3}, {%4,%5,%6,%7}, {%8,%9}, {%0,%1,%2,%3};"
        : "+f"(d[0]), "+f"(d[1]), "+f"(d[2]), "+f"(d[3])
        : "r"(a[0]), "r"(a[1]), "r"(a[2]), "r"(a[3]), "r"(b0), "r"(b1));
}
__device__ __forceinline__ void mbar_wait(uint32_t mbar, uint32_t parity) {
    asm volatile(
        "{\n\t.reg .pred P;\n\t"
        "W%=:\n\tmbarrier.try_wait.parity.acquire.cta.shared::cta.b64 P, [%0], %1, 0x989680;\n\t"
        "@P bra D%=;\n\tbra W%=;\n\tD%=:\n\t}"
        :: "r"(mbar), "r"(parity) : "memory");
}

// one 256B bulk copy per row; all 256 threads arrive on the mbarrier.
__device__ __forceinline__ void prefetch_tile(
    uint32_t ebase, uint32_t mbar, long long row_base, long long total_rows,
    int tid, int is64, const int* nb32, const long long* nb64)
{
    if (row_base < total_rows && tid < ROWS_PER_TILE) {
        long long gr = row_base + tid;
        long long nb = 0;
        if (gr < total_rows)
            nb = is64 ? __ldg(&nb64[gr]) : (long long)__ldg(&nb32[gr]);
        nb = nb < 0 ? 0 : (nb >= TABLE_SIZE ? TABLE_SIZE - 1 : nb);
        asm volatile("mbarrier.arrive.expect_tx.shared.b64 _, [%0], 256;"
                     :: "r"(mbar) : "memory");
        asm volatile(
            "cp.async.bulk.shared::cluster.global.mbarrier::complete_tx::bytes "
            "[%0], [%1], 256, [%2];"
            :: "r"(ebase + (uint32_t)tid * ROW_STRIDE),
               "l"((const char*)g_tab16 + nb * 256), "r"(mbar) : "memory");
    } else {
        asm volatile("mbarrier.arrive.shared.b64 _, [%0];" :: "r"(mbar) : "memory");
    }
}

__global__ __launch_bounds__(BLOCK_THREADS, 2) void meanpool_kernel(
    const void* __restrict__ neighbors_raw,
    const float* __restrict__ W,
    const float* __restrict__ b,
    float* __restrict__ out,
    int n_nodes)
{
    extern __shared__ char s[];
    const uint32_t sbase = smem_u32(s);
    float* sB = (float*)(s + B_OFF);

    const int tid  = threadIdx.x;
    const int wid  = tid >> 5;
    const int lane = tid & 31;
    const int warp_m = wid & 1;      // 64-row block
    const int warp_n = wid >> 1;     // 32-col block
    const int is64 = g_idx_is64;

    // ---- mbarriers ----
    if (tid == 0) {
        asm volatile("mbarrier.init.shared.b64 [%0], %1;"
                     :: "r"(sbase + MBAR_OFF), "r"(BLOCK_THREADS) : "memory");
        asm volatile("mbarrier.init.shared.b64 [%0], %1;"
                     :: "r"(sbase + MBAR_OFF + 8), "r"(BLOCK_THREADS) : "memory");
    }

    // ---- Stage W (f16, padded rows) + bias; zero E pad rows 125-127 once ----
    const float4* __restrict__ W4 = (const float4*)W;
    for (int i = tid; i < FDIM * 16; i += BLOCK_THREADS) {
        int f = i >> 4, c = i & 15;
        float4 v0 = __ldg(&W4[f * 32 + 2 * c]);
        float4 v1 = __ldg(&W4[f * 32 + 2 * c + 1]);
        uint4 w;
        w.x = pack_h2(v0.x, v0.y); w.y = pack_h2(v0.z, v0.w);
        w.z = pack_h2(v1.x, v1.y); w.w = pack_h2(v1.z, v1.w);
        *(uint4*)(s + W_OFF + ew(f, c)) = w;
    }
    if (tid < (M_PAD - ROWS_PER_TILE) * 16 * 2) {   // 96 threads, once
        int buf = tid >= (M_PAD - ROWS_PER_TILE) * 16;
        int j = tid - buf * (M_PAD - ROWS_PER_TILE) * 16;
        int r = ROWS_PER_TILE + (j >> 4), c = j & 15;
        *(uint4*)(s + (buf ? E1_OFF : E0_OFF) + ew(r, c)) = make_uint4(0u, 0u, 0u, 0u);
    }
    if (tid < FDIM) sB[tid] = __ldg(&b[tid]);

    // ---- Build pool A-fragments P[16x128] (block-ones), m16n8k16 A layout ----
    {
        int kc = tid >> 5, ln = tid & 31;
        int r = ln >> 2, kb = kc * 16 + (ln & 3) * 2;
        uint4 pf;
        uint32_t* pp = (uint32_t*)&pf;
        #pragma unroll
        for (int j = 0; j < 4; ++j) {
            int row = r + ((j & 1) << 3);
            int k = kb + ((j >> 1) << 3);
            float v0 = (row < NODES_PER_TILE && k >= 25 * row && k < 25 * row + 25) ? 1.f : 0.f;
            float v1 = (row < NODES_PER_TILE && k + 1 >= 25 * row && k + 1 < 25 * row + 25) ? 1.f : 0.f;
            pp[j] = pack_h2(v0, v1);
        }
        *(uint4*)(s + P_OFF + tid * 16) = pf;
    }
    __syncthreads();   // mbarrier init + staging visible

    // per-thread bias registers
    float bb[4][2];
    #pragma unroll
    for (int fn = 0; fn < 4; ++fn) {
        int c0 = warp_n * 32 + fn * 8 + (lane & 3) * 2;
        bb[fn][0] = sB[c0];
        bb[fn][1] = sB[c0 + 1];
    }

    const int* __restrict__       nb32 = (const int*)neighbors_raw;
    const long long* __restrict__ nb64 = (const long long*)neighbors_raw;

    const long long total_rows = (long long)n_nodes * S_SAMPLES;
    const int n_tiles = (int)((total_rows + ROWS_PER_TILE - 1) / ROWS_PER_TILE);

    // ---- prologue: prefetch t0 -> E0/mbar0, t1 -> E1/mbar1 ----
    prefetch_tile(sbase + E0_OFF, sbase + MBAR_OFF,
                  (long long)blockIdx.x * ROWS_PER_TILE, total_rows, tid, is64, nb32, nb64);
    prefetch_tile(sbase + E1_OFF, sbase + MBAR_OFF + 8,
                  ((long long)blockIdx.x + GRID_BLOCKS) * ROWS_PER_TILE,
                  total_rows, tid, is64, nb32, nb64);

    // per-lane ldmatrix address components (main MMA)
    const int a_row = (lane & 15);
    const int a_kc  = lane >> 4;
    const int b_n   = (lane & 7);
    const int b_kc  = (lane >> 3) & 1;
    const int b_fs  = lane >> 4;
    // pool ldmatrix components
    const int p_row = ((lane >> 3) & 1) * 8 + (lane & 7);
    const int p_cc  = ((wid * 16) + ((lane >> 4) << 3)) >> 3;

    int par0 = 0, par1 = 0;
    int cur = 0;
    for (int tile = blockIdx.x; tile < n_tiles; tile += GRID_BLOCKS, cur ^= 1) {
        const uint32_t ebase = sbase + (cur ? E1_OFF : E0_OFF);
        const char*    hb    = s + (cur ? E1_OFF : E0_OFF);
        const uint32_t mbar  = sbase + MBAR_OFF + (cur ? 8 : 0);

        // wait for this buffer's gather
        if (cur) { mbar_wait(mbar, par1); par1 ^= 1; }
        else     { mbar_wait(mbar, par0); par0 ^= 1; }

        // ---- main HMMA: 64x32 per warp ----
        float acc[4][4][4];
        #pragma unroll
        for (int fm = 0; fm < 4; ++fm)
            #pragma unroll
            for (int fn = 0; fn < 4; ++fn)
                #pragma unroll
                for (int j = 0; j < 4; ++j) acc[fm][fn][j] = 0.0f;

        #pragma unroll
        for (int ks = 0; ks < 8; ++ks) {
            uint32_t aF[4][4], bW[8];
            #pragma unroll
            for (int fm = 0; fm < 4; ++fm) {
                int row = warp_m * 64 + fm * 16 + a_row;
                ldm_x4(aF[fm], ebase + ew(row, ks * 2 + a_kc));
            }
            #pragma unroll
            for (int fp = 0; fp < 2; ++fp) {
                int n = warp_n * 32 + fp * 16 + b_fs * 8 + b_n;
                ldm_x4(bW + fp * 4, sbase + W_OFF + ew(n, ks * 2 + b_kc));
            }
            #pragma unroll
            for (int fm = 0; fm < 4; ++fm)
                #pragma unroll
                for (int fn = 0; fn < 4; ++fn)
                    mma_f16(acc[fm][fn], aF[fm], bW[fn * 2], bW[fn * 2 + 1]);
        }
        __syncthreads();   // all E reads done before H aliases this buffer

        // ---- bias+relu -> H (f16, aliases E[cur]) ----
        #pragma unroll
        for (int fm = 0; fm < 4; ++fm) {
            int r0 = warp_m * 64 + fm * 16 + (lane >> 2);
            #pragma unroll
            for (int fn = 0; fn < 4; ++fn) {
                int c0 = warp_n * 32 + fn * 8 + (lane & 3) * 2;
                uint32_t h0 = pack_h2(fmaxf(acc[fm][fn][0] + bb[fn][0], 0.f),
                                      fmaxf(acc[fm][fn][1] + bb[fn][1], 0.f));
                uint32_t h1 = pack_h2(fmaxf(acc[fm][fn][2] + bb[fn][0], 0.f),
                                      fmaxf(acc[fm][fn][3] + bb[fn][1], 0.f));
                *(uint32_t*)(hb + (uint32_t)r0 * ROW_STRIDE + c0 * 2)       = h0;
                *(uint32_t*)(hb + (uint32_t)(r0 + 8) * ROW_STRIDE + c0 * 2) = h1;
            }
        }
        __syncthreads();

        // ---- pool MMA: D[5x16 per warp] = P @ H ----
        {
            float dp0[4] = {0.f, 0.f, 0.f, 0.f}, dp1[4] = {0.f, 0.f, 0.f, 0.f};
            #pragma unroll
            for (int kc = 0; kc < 8; ++kc) {
                uint32_t pf[4], bf[4];
                *(uint4*)pf = *(const uint4*)(s + P_OFF + ((kc << 5) + lane) * 16);
                ldm_x4_t(bf, ebase + ew(kc * 16 + p_row, p_cc));
                mma_f16(dp0, pf, bf[0], bf[1]);
                mma_f16(dp1, pf, bf[2], bf[3]);
            }
            int g = lane >> 2;
            if (g < NODES_PER_TILE) {
                long long n = (long long)tile * NODES_PER_TILE + g;
                if (n < n_nodes) {
                    const float sc = 1.0f / (float)S_SAMPLES;
                    int cb = wid * 16 + (lane & 3) * 2;
                    *(float2*)&out[n * FDIM + cb]     = make_float2(dp0[0] * sc, dp0[1] * sc);
                    *(float2*)&out[n * FDIM + cb + 8] = make_float2(dp1[0] * sc, dp1[1] * sc);
                }
            }
        }
        __syncthreads();   // pool reads done before prefetch overwrites

        // ---- prefetch tile t+2 into this buffer ----
        prefetch_tile(ebase, mbar, ((long long)tile + 2 * GRID_BLOCKS) * ROWS_PER_TILE,
                      total_rows, tid, is64, nb32, nb64);
    }
}

extern "C" void kernel_launch(void* const* d_in, const int* in_sizes, int n_in,
                              void* d_out, int out_size) {
    const void*  neighbors = d_in[0];
    const float* emb_table = (const float*)d_in[1];
    const float* W         = (const float*)d_in[2];
    const float* b         = (const float*)d_in[3];
    float*       out       = (float*)d_out;

    const int n_nodes = in_sizes[0] / S_SAMPLES;

    cudaFuncSetAttribute(meanpool_kernel,
                         cudaFuncAttributeMaxDynamicSharedMemorySize, SMEM_TOTAL);

    convert_table<<<(TABLE_SIZE * 16 + 255) / 256, 256>>>((const float4*)emb_table,
                                                          (const int*)neighbors);
    meanpool_kernel<<<GRID_BLOCKS, BLOCK_THREADS, SMEM_TOTAL>>>(
        neighbors, W, b, out, n_nodes);
}

// round 13
// speedup vs baseline: 11.7139x; 1.0429x over previous
#include <cuda_runtime.h>
#include <cuda_fp16.h>
#include <cstdint>

// out[n,f] = (1/25) * sum_s relu( dot(E[nbr[n,s],:], W[f,:]) + b[f] )
// f16 HMMA (fp32 accum); table pre-converted to a __device__ f16 mirror.
// Gather: ONE cp.async.bulk (256B) per embedding row into a 272B-stride
// E tile, completion via mbarrier expect_tx. M=128 tiles (5 nodes),
// 256 thr = 8 warps (2m x 4n), 2 CTAs/SM. H (f16) aliases consumed E and is
// written with stmatrix.x4; mean-pool = MMA against block-ones P.

#define S_SAMPLES 25
#define FDIM 128
#define TABLE_SIZE 100000
#define ROWS_PER_TILE 125
#define NODES_PER_TILE 5
#define M_PAD 128
#define BLOCK_THREADS 256
#define GRID_BLOCKS 296            // 2 per SM

#define ROW_STRIDE 272             // 256B data + 16B pad -> conflict-free ldmatrix
#define TILE_BYTES (M_PAD * ROW_STRIDE)   // 34816

#define E0_OFF 0
#define E1_OFF TILE_BYTES          // 34816
#define W_OFF  (2 * TILE_BYTES)    // 69632
#define B_OFF  (3 * TILE_BYTES)    // 104448 (bias 512B)
#define P_OFF  (B_OFF + 512)       // 104960 (pool A-frags 4KB)
#define MBAR_OFF (P_OFF + 4096)    // 109056 (2 x 8B)
#define SMEM_TOTAL (MBAR_OFF + 32)

__device__ int g_idx_is64;
__device__ uint4 g_tab16[TABLE_SIZE * 16];   // f16 table mirror, 256B rows

__device__ __forceinline__ uint32_t pack_h2(float a, float b) {
    uint32_t r;
    asm("{ .reg .b16 x, y; cvt.rn.f16.f32 x, %1; cvt.rn.f16.f32 y, %2;"
        " mov.b32 %0, {x, y}; }" : "=r"(r) : "f"(a), "f"(b));
    return r;
}

// fp32 table -> f16 mirror; block 0 thread 0 also detects the index dtype.
__global__ void convert_table(const float4* __restrict__ table4,
                              const int* __restrict__ nb32) {
    if (blockIdx.x == 0 && threadIdx.x == 0) {
        int is64 = 1;
        #pragma unroll
        for (int i = 1; i < 64; i += 2) if (nb32[i] != 0) is64 = 0;
        g_idx_is64 = is64;
    }
    int i = blockIdx.x * blockDim.x + threadIdx.x;     // 16B chunk index
    if (i >= TABLE_SIZE * 16) return;
    float4 v0 = __ldg(&table4[2 * i]);
    float4 v1 = __ldg(&table4[2 * i + 1]);
    uint4 w;
    w.x = pack_h2(v0.x, v0.y); w.y = pack_h2(v0.z, v0.w);
    w.z = pack_h2(v1.x, v1.y); w.w = pack_h2(v1.z, v1.w);
    g_tab16[i] = w;
}

// ---------------- helpers ----------------
__device__ __forceinline__ uint32_t smem_u32(const void* p) {
    uint32_t a;
    asm("{ .reg .u64 t; cvta.to.shared.u64 t, %1; cvt.u32.u64 %0, t; }" : "=r"(a) : "l"(p));
    return a;
}
// padded-stride addressing (chunk in 16B units)
__device__ __forceinline__ uint32_t ew(int row, int chunk) {
    return (uint32_t)row * ROW_STRIDE + (uint32_t)chunk * 16u;
}
__device__ __forceinline__ void ldm_x4(uint32_t* a, uint32_t addr) {
    asm volatile("ldmatrix.sync.aligned.m8n8.x4.shared.b16 {%0,%1,%2,%3}, [%4];"
                 : "=r"(a[0]), "=r"(a[1]), "=r"(a[2]), "=r"(a[3]) : "r"(addr));
}
__device__ __forceinline__ void ldm_x4_t(uint32_t* a, uint32_t addr) {
    asm volatile("ldmatrix.sync.aligned.m8n8.x4.trans.shared.b16 {%0,%1,%2,%3}, [%4];"
                 : "=r"(a[0]), "=r"(a[1]), "=r"(a[2]), "=r"(a[3]) : "r"(addr));
}
__device__ __forceinline__ void stm_x4(uint32_t addr, const uint32_t* r) {
    asm volatile("stmatrix.sync.aligned.m8n8.x4.shared.b16 [%0], {%1,%2,%3,%4};"
                 :: "r"(addr), "r"(r[0]), "r"(r[1]), "r"(r[2]), "r"(r[3]) : "memory");
}
__device__ __forceinline__ void mma_f16(float* d, const uint32_t* a,
                                        uint32_t b0, uint32_t b1) {
    asm volatile(
        "mma.sync.aligned.m16n8k16.row.col.f32.f16.f16.f32 "
        "{%0,%1,%2,%3}, {%4,%5,%6,%7}, {%8,%9}, {%0,%1,%2,%3};"
        : "+f"(d[0]), "+f"(d[1]), "+f"(d[2]), "+f"(d[3])
        : "r"(a[0]), "r"(a[1]), "r"(a[2]), "r"(a[3]), "r"(b0), "r"(b1));
}
__device__ __forceinline__ void mbar_wait(uint32_t mbar, uint32_t parity) {
    asm volatile(
        "{\n\t.reg .pred P;\n\t"
        "W%=:\n\tmbarrier.try_wait.parity.acquire.cta.shared::cta.b64 P, [%0], %1, 0x989680;\n\t"
        "@P bra D%=;\n\tbra W%=;\n\tD%=:\n\t}"
        :: "r"(mbar), "r"(parity) : "memory");
}

// one 256B bulk copy per row; all 256 threads arrive on the mbarrier.
__device__ __forceinline__ void prefetch_tile(
    uint32_t ebase, uint32_t mbar, long long row_base, long long total_rows,
    int tid, int is64, const int* nb32, const long long* nb64)
{
    if (row_base < total_rows && tid < ROWS_PER_TILE) {
        long long gr = row_base + tid;
        long long nb = 0;
        if (gr < total_rows)
            nb = is64 ? __ldg(&nb64[gr]) : (long long)__ldg(&nb32[gr]);
        nb = nb < 0 ? 0 : (nb >= TABLE_SIZE ? TABLE_SIZE - 1 : nb);
        asm volatile("mbarrier.arrive.expect_tx.shared.b64 _, [%0], 256;"
                     :: "r"(mbar) : "memory");
        asm volatile(
            "cp.async.bulk.shared::cluster.global.mbarrier::complete_tx::bytes "
            "[%0], [%1], 256, [%2];"
            :: "r"(ebase + (uint32_t)tid * ROW_STRIDE),
               "l"((const char*)g_tab16 + nb * 256), "r"(mbar) : "memory");
    } else {
        asm volatile("mbarrier.arrive.shared.b64 _, [%0];" :: "r"(mbar) : "memory");
    }
}

__global__ __launch_bounds__(BLOCK_THREADS, 2) void meanpool_kernel(
    const void* __restrict__ neighbors_raw,
    const float* __restrict__ W,
    const float* __restrict__ b,
    float* __restrict__ out,
    int n_nodes)
{
    extern __shared__ char s[];
    const uint32_t sbase = smem_u32(s);
    float* sB = (float*)(s + B_OFF);

    const int tid  = threadIdx.x;
    const int wid  = tid >> 5;
    const int lane = tid & 31;
    const int warp_m = wid & 1;      // 64-row block
    const int warp_n = wid >> 1;     // 32-col block
    const int is64 = g_idx_is64;

    // ---- mbarriers ----
    if (tid == 0) {
        asm volatile("mbarrier.init.shared.b64 [%0], %1;"
                     :: "r"(sbase + MBAR_OFF), "r"(BLOCK_THREADS) : "memory");
        asm volatile("mbarrier.init.shared.b64 [%0], %1;"
                     :: "r"(sbase + MBAR_OFF + 8), "r"(BLOCK_THREADS) : "memory");
    }

    // ---- Stage W (f16, padded rows) + bias; zero E pad rows 125-127 once ----
    const float4* __restrict__ W4 = (const float4*)W;
    for (int i = tid; i < FDIM * 16; i += BLOCK_THREADS) {
        int f = i >> 4, c = i & 15;
        float4 v0 = __ldg(&W4[f * 32 + 2 * c]);
        float4 v1 = __ldg(&W4[f * 32 + 2 * c + 1]);
        uint4 w;
        w.x = pack_h2(v0.x, v0.y); w.y = pack_h2(v0.z, v0.w);
        w.z = pack_h2(v1.x, v1.y); w.w = pack_h2(v1.z, v1.w);
        *(uint4*)(s + W_OFF + ew(f, c)) = w;
    }
    if (tid < (M_PAD - ROWS_PER_TILE) * 16 * 2) {   // 96 threads, once
        int buf = tid >= (M_PAD - ROWS_PER_TILE) * 16;
        int j = tid - buf * (M_PAD - ROWS_PER_TILE) * 16;
        int r = ROWS_PER_TILE + (j >> 4), c = j & 15;
        *(uint4*)(s + (buf ? E1_OFF : E0_OFF) + ew(r, c)) = make_uint4(0u, 0u, 0u, 0u);
    }
    if (tid < FDIM) sB[tid] = __ldg(&b[tid]);

    // ---- Build pool A-fragments P[16x128] (block-ones), m16n8k16 A layout ----
    {
        int kc = tid >> 5, ln = tid & 31;
        int r = ln >> 2, kb = kc * 16 + (ln & 3) * 2;
        uint4 pf;
        uint32_t* pp = (uint32_t*)&pf;
        #pragma unroll
        for (int j = 0; j < 4; ++j) {
            int row = r + ((j & 1) << 3);
            int k = kb + ((j >> 1) << 3);
            float v0 = (row < NODES_PER_TILE && k >= 25 * row && k < 25 * row + 25) ? 1.f : 0.f;
            float v1 = (row < NODES_PER_TILE && k + 1 >= 25 * row && k + 1 < 25 * row + 25) ? 1.f : 0.f;
            pp[j] = pack_h2(v0, v1);
        }
        *(uint4*)(s + P_OFF + tid * 16) = pf;
    }
    __syncthreads();   // mbarrier init + staging visible

    // per-thread bias registers
    float bb[4][2];
    #pragma unroll
    for (int fn = 0; fn < 4; ++fn) {
        int c0 = warp_n * 32 + fn * 8 + (lane & 3) * 2;
        bb[fn][0] = sB[c0];
        bb[fn][1] = sB[c0 + 1];
    }

    const int* __restrict__       nb32 = (const int*)neighbors_raw;
    const long long* __restrict__ nb64 = (const long long*)neighbors_raw;

    const long long total_rows = (long long)n_nodes * S_SAMPLES;
    const int n_tiles = (int)((total_rows + ROWS_PER_TILE - 1) / ROWS_PER_TILE);

    // ---- prologue: prefetch t0 -> E0/mbar0, t1 -> E1/mbar1 ----
    prefetch_tile(sbase + E0_OFF, sbase + MBAR_OFF,
                  (long long)blockIdx.x * ROWS_PER_TILE, total_rows, tid, is64, nb32, nb64);
    prefetch_tile(sbase + E1_OFF, sbase + MBAR_OFF + 8,
                  ((long long)blockIdx.x + GRID_BLOCKS) * ROWS_PER_TILE,
                  total_rows, tid, is64, nb32, nb64);

    // per-lane ldmatrix address components (main MMA)
    const int a_row = (lane & 15);
    const int a_kc  = lane >> 4;
    const int b_n   = (lane & 7);
    const int b_kc  = (lane >> 3) & 1;
    const int b_fs  = lane >> 4;
    // pool ldmatrix components
    const int p_row = ((lane >> 3) & 1) * 8 + (lane & 7);
    const int p_cc  = ((wid * 16) + ((lane >> 4) << 3)) >> 3;
    // stmatrix per-lane base: row (lane&7), col-matrix (lane>>3)*8 halves
    const uint32_t stm_lane = (uint32_t)(lane & 7) * ROW_STRIDE +
                              (uint32_t)(lane >> 3) * 16u +
                              (uint32_t)warp_m * 64u * ROW_STRIDE +
                              (uint32_t)warp_n * 64u;

    int par0 = 0, par1 = 0;
    int cur = 0;
    for (int tile = blockIdx.x; tile < n_tiles; tile += GRID_BLOCKS, cur ^= 1) {
        const uint32_t ebase = sbase + (cur ? E1_OFF : E0_OFF);
        const uint32_t mbar  = sbase + MBAR_OFF + (cur ? 8 : 0);

        // wait for this buffer's gather
        if (cur) { mbar_wait(mbar, par1); par1 ^= 1; }
        else     { mbar_wait(mbar, par0); par0 ^= 1; }

        // ---- main HMMA: 64x32 per warp ----
        float acc[4][4][4];
        #pragma unroll
        for (int fm = 0; fm < 4; ++fm)
            #pragma unroll
            for (int fn = 0; fn < 4; ++fn)
                #pragma unroll
                for (int j = 0; j < 4; ++j) acc[fm][fn][j] = 0.0f;

        #pragma unroll
        for (int ks = 0; ks < 8; ++ks) {
            uint32_t aF[4][4], bW[8];
            #pragma unroll
            for (int fm = 0; fm < 4; ++fm) {
                int row = warp_m * 64 + fm * 16 + a_row;
                ldm_x4(aF[fm], ebase + ew(row, ks * 2 + a_kc));
            }
            #pragma unroll
            for (int fp = 0; fp < 2; ++fp) {
                int n = warp_n * 32 + fp * 16 + b_fs * 8 + b_n;
                ldm_x4(bW + fp * 4, sbase + W_OFF + ew(n, ks * 2 + b_kc));
            }
            #pragma unroll
            for (int fm = 0; fm < 4; ++fm)
                #pragma unroll
                for (int fn = 0; fn < 4; ++fn)
                    mma_f16(acc[fm][fn], aF[fm], bW[fn * 2], bW[fn * 2 + 1]);
        }
        __syncthreads();   // all E reads done before H aliases this buffer

        // ---- bias+relu -> H via stmatrix (f16, aliases E[cur]) ----
        #pragma unroll
        for (int fm = 0; fm < 4; ++fm) {
            uint32_t h0[4], h1[4];
            #pragma unroll
            for (int fn = 0; fn < 4; ++fn) {
                h0[fn] = pack_h2(fmaxf(acc[fm][fn][0] + bb[fn][0], 0.f),
                                 fmaxf(acc[fm][fn][1] + bb[fn][1], 0.f));
                h1[fn] = pack_h2(fmaxf(acc[fm][fn][2] + bb[fn][0], 0.f),
                                 fmaxf(acc[fm][fn][3] + bb[fn][1], 0.f));
            }
            uint32_t a0 = ebase + stm_lane + (uint32_t)(fm * 16) * ROW_STRIDE;
            stm_x4(a0, h0);
            stm_x4(a0 + 8u * ROW_STRIDE, h1);
        }
        __syncthreads();

        // ---- pool MMA: D[5x16 per warp] = P @ H ----
        {
            float dp0[4] = {0.f, 0.f, 0.f, 0.f}, dp1[4] = {0.f, 0.f, 0.f, 0.f};
            #pragma unroll
            for (int kc = 0; kc < 8; ++kc) {
                uint32_t pf[4], bf[4];
                *(uint4*)pf = *(const uint4*)(s + P_OFF + ((kc << 5) + lane) * 16);
                ldm_x4_t(bf, ebase + ew(kc * 16 + p_row, p_cc));
                mma_f16(dp0, pf, bf[0], bf[1]);
                mma_f16(dp1, pf, bf[2], bf[3]);
            }
            int g = lane >> 2;
            if (g < NODES_PER_TILE) {
                long long n = (long long)tile * NODES_PER_TILE + g;
                if (n < n_nodes) {
                    const float sc = 1.0f / (float)S_SAMPLES;
                    int cb = wid * 16 + (lane & 3) * 2;
                    *(float2*)&out[n * FDIM + cb]     = make_float2(dp0[0] * sc, dp0[1] * sc);
                    *(float2*)&out[n * FDIM + cb + 8] = make_float2(dp1[0] * sc, dp1[1] * sc);
                }
            }
        }
        __syncthreads();   // pool reads done before prefetch overwrites

        // ---- prefetch tile t+2 into this buffer ----
        prefetch_tile(ebase, mbar, ((long long)tile + 2 * GRID_BLOCKS) * ROWS_PER_TILE,
                      total_rows, tid, is64, nb32, nb64);
    }
}

extern "C" void kernel_launch(void* const* d_in, const int* in_sizes, int n_in,
                              void* d_out, int out_size) {
    const void*  neighbors = d_in[0];
    const float* emb_table = (const float*)d_in[1];
    const float* W         = (const float*)d_in[2];
    const float* b         = (const float*)d_in[3];
    float*       out       = (float*)d_out;

    const int n_nodes = in_sizes[0] / S_SAMPLES;

    cudaFuncSetAttribute(meanpool_kernel,
                         cudaFuncAttributeMaxDynamicSharedMemorySize, SMEM_TOTAL);

    convert_table<<<(TABLE_SIZE * 16 + 255) / 256, 256>>>((const float4*)emb_table,
                                                          (const int*)neighbors);
    meanpool_kernel<<<GRID_BLOCKS, BLOCK_THREADS, SMEM_TOTAL>>>(
        neighbors, W, b, out, n_nodes);
}

// round 14
// speedup vs baseline: 11.7240x; 1.0009x over previous
#include <cuda_runtime.h>
#include <cuda_fp16.h>
#include <cstdint>

// out[n,f] = (1/25) * sum_s relu( dot(E[nbr[n,s],:], W[f,:]) + b[f] )
// f16 HMMA (fp32 accum); table pre-converted to a __device__ f16 mirror.
// Gather: ONE cp.async.bulk (256B) per embedding row into a 272B-stride
// E tile, completion via mbarrier expect_tx. M=128 tiles (5 nodes),
// 256 thr = 8 warps (2m x 4n), 2 CTAs/SM. H (f16) aliases consumed E and is
// written with stmatrix.x4; mean-pool = MMA against block-ones P.
// All f32->f16x2 packing via single-instruction cvt.rn.f16x2.f32.

#define S_SAMPLES 25
#define FDIM 128
#define TABLE_SIZE 100000
#define ROWS_PER_TILE 125
#define NODES_PER_TILE 5
#define M_PAD 128
#define BLOCK_THREADS 256
#define GRID_BLOCKS 296            // 2 per SM

#define ROW_STRIDE 272             // 256B data + 16B pad -> conflict-free ldmatrix
#define TILE_BYTES (M_PAD * ROW_STRIDE)   // 34816

#define E0_OFF 0
#define E1_OFF TILE_BYTES          // 34816
#define W_OFF  (2 * TILE_BYTES)    // 69632
#define B_OFF  (3 * TILE_BYTES)    // 104448 (bias 512B)
#define P_OFF  (B_OFF + 512)       // 104960 (pool A-frags 4KB)
#define MBAR_OFF (P_OFF + 4096)    // 109056 (2 x 8B)
#define SMEM_TOTAL (MBAR_OFF + 32)

__device__ int g_idx_is64;
__device__ uint4 g_tab16[TABLE_SIZE * 16];   // f16 table mirror, 256B rows

// single-instruction pack: d = {lo=a, hi=b} as f16x2
__device__ __forceinline__ uint32_t pack_h2(float a, float b) {
    uint32_t r;
    asm("cvt.rn.f16x2.f32 %0, %2, %1;" : "=r"(r) : "f"(a), "f"(b));
    return r;
}

// fp32 table -> f16 mirror; block 0 thread 0 also detects the index dtype.
__global__ void convert_table(const float4* __restrict__ table4,
                              const int* __restrict__ nb32) {
    if (blockIdx.x == 0 && threadIdx.x == 0) {
        int is64 = 1;
        #pragma unroll
        for (int i = 1; i < 64; i += 2) if (nb32[i] != 0) is64 = 0;
        g_idx_is64 = is64;
    }
    int i = blockIdx.x * blockDim.x + threadIdx.x;     // 16B chunk index
    if (i >= TABLE_SIZE * 16) return;
    float4 v0 = __ldg(&table4[2 * i]);
    float4 v1 = __ldg(&table4[2 * i + 1]);
    uint4 w;
    w.x = pack_h2(v0.x, v0.y); w.y = pack_h2(v0.z, v0.w);
    w.z = pack_h2(v1.x, v1.y); w.w = pack_h2(v1.z, v1.w);
    g_tab16[i] = w;
}

// ---------------- helpers ----------------
__device__ __forceinline__ uint32_t smem_u32(const void* p) {
    uint32_t a;
    asm("{ .reg .u64 t; cvta.to.shared.u64 t, %1; cvt.u32.u64 %0, t; }" : "=r"(a) : "l"(p));
    return a;
}
// padded-stride addressing (chunk in 16B units)
__device__ __forceinline__ uint32_t ew(int row, int chunk) {
    return (uint32_t)row * ROW_STRIDE + (uint32_t)chunk * 16u;
}
__device__ __forceinline__ void ldm_x4(uint32_t* a, uint32_t addr) {
    asm volatile("ldmatrix.sync.aligned.m8n8.x4.shared.b16 {%0,%1,%2,%3}, [%4];"
                 : "=r"(a[0]), "=r"(a[1]), "=r"(a[2]), "=r"(a[3]) : "r"(addr));
}
__device__ __forceinline__ void ldm_x4_t(uint32_t* a, uint32_t addr) {
    asm volatile("ldmatrix.sync.aligned.m8n8.x4.trans.shared.b16 {%0,%1,%2,%3}, [%4];"
                 : "=r"(a[0]), "=r"(a[1]), "=r"(a[2]), "=r"(a[3]) : "r"(addr));
}
__device__ __forceinline__ void stm_x4(uint32_t addr, const uint32_t* r) {
    asm volatile("stmatrix.sync.aligned.m8n8.x4.shared.b16 [%0], {%1,%2,%3,%4};"
                 :: "r"(addr), "r"(r[0]), "r"(r[1]), "r"(r[2]), "r"(r[3]) : "memory");
}
__device__ __forceinline__ void mma_f16(float* d, const uint32_t* a,
                                        uint32_t b0, uint32_t b1) {
    asm volatile(
        "mma.sync.aligned.m16n8k16.row.col.f32.f16.f16.f32 "
        "{%0,%1,%2,%3}, {%4,%5,%6,%7}, {%8,%9}, {%0,%1,%2,%3};"
        : "+f"(d[0]), "+f"(d[1]), "+f"(d[2]), "+f"(d[3])
        : "r"(a[0]), "r"(a[1]), "r"(a[2]), "r"(a[3]), "r"(b0), "r"(b1));
}
__device__ __forceinline__ void mbar_wait(uint32_t mbar, uint32_t parity) {
    asm volatile(
        "{\n\t.reg .pred P;\n\t"
        "W%=:\n\tmbarrier.try_wait.parity.acquire.cta.shared::cta.b64 P, [%0], %1, 0x989680;\n\t"
        "@P bra D%=;\n\tbra W%=;\n\tD%=:\n\t}"
        :: "r"(mbar), "r"(parity) : "memory");
}

// one 256B bulk copy per row; all 256 threads arrive on the mbarrier.
__device__ __forceinline__ void prefetch_tile(
    uint32_t ebase, uint32_t mbar, long long row_base, long long total_rows,
    int tid, int is64, const int* nb32, const long long* nb64)
{
    if (row_base < total_rows && tid < ROWS_PER_TILE) {
        long long gr = row_base + tid;
        long long nb = 0;
        if (gr < total_rows)
            nb = is64 ? __ldg(&nb64[gr]) : (long long)__ldg(&nb32[gr]);
        nb = nb < 0 ? 0 : (nb >= TABLE_SIZE ? TABLE_SIZE - 1 : nb);
        asm volatile("mbarrier.arrive.expect_tx.shared.b64 _, [%0], 256;"
                     :: "r"(mbar) : "memory");
        asm volatile(
            "cp.async.bulk.shared::cluster.global.mbarrier::complete_tx::bytes "
            "[%0], [%1], 256, [%2];"
            :: "r"(ebase + (uint32_t)tid * ROW_STRIDE),
               "l"((const char*)g_tab16 + nb * 256), "r"(mbar) : "memory");
    } else {
        asm volatile("mbarrier.arrive.shared.b64 _, [%0];" :: "r"(mbar) : "memory");
    }
}

__global__ __launch_bounds__(BLOCK_THREADS, 2) void meanpool_kernel(
    const void* __restrict__ neighbors_raw,
    const float* __restrict__ W,
    const float* __restrict__ b,
    float* __restrict__ out,
    int n_nodes)
{
    extern __shared__ char s[];
    const uint32_t sbase = smem_u32(s);
    float* sB = (float*)(s + B_OFF);

    const int tid  = threadIdx.x;
    const int wid  = tid >> 5;
    const int lane = tid & 31;
    const int warp_m = wid & 1;      // 64-row block
    const int warp_n = wid >> 1;     // 32-col block
    const int is64 = g_idx_is64;

    // ---- mbarriers ----
    if (tid == 0) {
        asm volatile("mbarrier.init.shared.b64 [%0], %1;"
                     :: "r"(sbase + MBAR_OFF), "r"(BLOCK_THREADS) : "memory");
        asm volatile("mbarrier.init.shared.b64 [%0], %1;"
                     :: "r"(sbase + MBAR_OFF + 8), "r"(BLOCK_THREADS) : "memory");
    }

    // ---- Stage W (f16, padded rows) + bias; zero E pad rows 125-127 once ----
    const float4* __restrict__ W4 = (const float4*)W;
    for (int i = tid; i < FDIM * 16; i += BLOCK_THREADS) {
        int f = i >> 4, c = i & 15;
        float4 v0 = __ldg(&W4[f * 32 + 2 * c]);
        float4 v1 = __ldg(&W4[f * 32 + 2 * c + 1]);
        uint4 w;
        w.x = pack_h2(v0.x, v0.y); w.y = pack_h2(v0.z, v0.w);
        w.z = pack_h2(v1.x, v1.y); w.w = pack_h2(v1.z, v1.w);
        *(uint4*)(s + W_OFF + ew(f, c)) = w;
    }
    if (tid < (M_PAD - ROWS_PER_TILE) * 16 * 2) {   // 96 threads, once
        int buf = tid >= (M_PAD - ROWS_PER_TILE) * 16;
        int j = tid - buf * (M_PAD - ROWS_PER_TILE) * 16;
        int r = ROWS_PER_TILE + (j >> 4), c = j & 15;
        *(uint4*)(s + (buf ? E1_OFF : E0_OFF) + ew(r, c)) = make_uint4(0u, 0u, 0u, 0u);
    }
    if (tid < FDIM) sB[tid] = __ldg(&b[tid]);

    // ---- Build pool A-fragments P[16x128] (block-ones), m16n8k16 A layout ----
    {
        int kc = tid >> 5, ln = tid & 31;
        int r = ln >> 2, kb = kc * 16 + (ln & 3) * 2;
        uint4 pf;
        uint32_t* pp = (uint32_t*)&pf;
        #pragma unroll
        for (int j = 0; j < 4; ++j) {
            int row = r + ((j & 1) << 3);
            int k = kb + ((j >> 1) << 3);
            float v0 = (row < NODES_PER_TILE && k >= 25 * row && k < 25 * row + 25) ? 1.f : 0.f;
            float v1 = (row < NODES_PER_TILE && k + 1 >= 25 * row && k + 1 < 25 * row + 25) ? 1.f : 0.f;
            pp[j] = pack_h2(v0, v1);
        }
        *(uint4*)(s + P_OFF + tid * 16) = pf;
    }
    __syncthreads();   // mbarrier init + staging visible

    // per-thread bias registers
    float bb[4][2];
    #pragma unroll
    for (int fn = 0; fn < 4; ++fn) {
        int c0 = warp_n * 32 + fn * 8 + (lane & 3) * 2;
        bb[fn][0] = sB[c0];
        bb[fn][1] = sB[c0 + 1];
    }

    const int* __restrict__       nb32 = (const int*)neighbors_raw;
    const long long* __restrict__ nb64 = (const long long*)neighbors_raw;

    const long long total_rows = (long long)n_nodes * S_SAMPLES;
    const int n_tiles = (int)((total_rows + ROWS_PER_TILE - 1) / ROWS_PER_TILE);

    // ---- prologue: prefetch t0 -> E0/mbar0, t1 -> E1/mbar1 ----
    prefetch_tile(sbase + E0_OFF, sbase + MBAR_OFF,
                  (long long)blockIdx.x * ROWS_PER_TILE, total_rows, tid, is64, nb32, nb64);
    prefetch_tile(sbase + E1_OFF, sbase + MBAR_OFF + 8,
                  ((long long)blockIdx.x + GRID_BLOCKS) * ROWS_PER_TILE,
                  total_rows, tid, is64, nb32, nb64);

    // per-lane ldmatrix address components (main MMA)
    const int a_row = (lane & 15);
    const int a_kc  = lane >> 4;
    const int b_n   = (lane & 7);
    const int b_kc  = (lane >> 3) & 1;
    const int b_fs  = lane >> 4;
    // pool ldmatrix components
    const int p_row = ((lane >> 3) & 1) * 8 + (lane & 7);
    const int p_cc  = ((wid * 16) + ((lane >> 4) << 3)) >> 3;
    // stmatrix per-lane base: row (lane&7), col-matrix (lane>>3)
    const uint32_t stm_lane = (uint32_t)(lane & 7) * ROW_STRIDE +
                              (uint32_t)(lane >> 3) * 16u +
                              (uint32_t)warp_m * 64u * ROW_STRIDE +
                              (uint32_t)warp_n * 64u;

    int par0 = 0, par1 = 0;
    int cur = 0;
    for (int tile = blockIdx.x; tile < n_tiles; tile += GRID_BLOCKS, cur ^= 1) {
        const uint32_t ebase = sbase + (cur ? E1_OFF : E0_OFF);
        const uint32_t mbar  = sbase + MBAR_OFF + (cur ? 8 : 0);

        // wait for this buffer's gather
        if (cur) { mbar_wait(mbar, par1); par1 ^= 1; }
        else     { mbar_wait(mbar, par0); par0 ^= 1; }

        // ---- main HMMA: 64x32 per warp ----
        float acc[4][4][4];
        #pragma unroll
        for (int fm = 0; fm < 4; ++fm)
            #pragma unroll
            for (int fn = 0; fn < 4; ++fn)
                #pragma unroll
                for (int j = 0; j < 4; ++j) acc[fm][fn][j] = 0.0f;

        #pragma unroll
        for (int ks = 0; ks < 8; ++ks) {
            uint32_t aF[4][4], bW[8];
            #pragma unroll
            for (int fm = 0; fm < 4; ++fm) {
                int row = warp_m * 64 + fm * 16 + a_row;
                ldm_x4(aF[fm], ebase + ew(row, ks * 2 + a_kc));
            }
            #pragma unroll
            for (int fp = 0; fp < 2; ++fp) {
                int n = warp_n * 32 + fp * 16 + b_fs * 8 + b_n;
                ldm_x4(bW + fp * 4, sbase + W_OFF + ew(n, ks * 2 + b_kc));
            }
            #pragma unroll
            for (int fm = 0; fm < 4; ++fm)
                #pragma unroll
                for (int fn = 0; fn < 4; ++fn)
                    mma_f16(acc[fm][fn], aF[fm], bW[fn * 2], bW[fn * 2 + 1]);
        }
        __syncthreads();   // all E reads done before H aliases this buffer

        // ---- bias+relu -> H via stmatrix (f16, aliases E[cur]) ----
        #pragma unroll
        for (int fm = 0; fm < 4; ++fm) {
            uint32_t h0[4], h1[4];
            #pragma unroll
            for (int fn = 0; fn < 4; ++fn) {
                h0[fn] = pack_h2(fmaxf(acc[fm][fn][0] + bb[fn][0], 0.f),
                                 fmaxf(acc[fm][fn][1] + bb[fn][1], 0.f));
                h1[fn] = pack_h2(fmaxf(acc[fm][fn][2] + bb[fn][0], 0.f),
                                 fmaxf(acc[fm][fn][3] + bb[fn][1], 0.f));
            }
            uint32_t a0 = ebase + stm_lane + (uint32_t)(fm * 16) * ROW_STRIDE;
            stm_x4(a0, h0);
            stm_x4(a0 + 8u * ROW_STRIDE, h1);
        }
        __syncthreads();

        // ---- pool MMA: D[5x16 per warp] = P @ H ----
        {
            float dp0[4] = {0.f, 0.f, 0.f, 0.f}, dp1[4] = {0.f, 0.f, 0.f, 0.f};
            #pragma unroll
            for (int kc = 0; kc < 8; ++kc) {
                uint32_t pf[4], bf[4];
                *(uint4*)pf = *(const uint4*)(s + P_OFF + ((kc << 5) + lane) * 16);
                ldm_x4_t(bf, ebase + ew(kc * 16 + p_row, p_cc));
                mma_f16(dp0, pf, bf[0], bf[1]);
                mma_f16(dp1, pf, bf[2], bf[3]);
            }
            int g = lane >> 2;
            if (g < NODES_PER_TILE) {
                long long n = (long long)tile * NODES_PER_TILE + g;
                if (n < n_nodes) {
                    const float sc = 1.0f / (float)S_SAMPLES;
                    int cb = wid * 16 + (lane & 3) * 2;
                    *(float2*)&out[n * FDIM + cb]     = make_float2(dp0[0] * sc, dp0[1] * sc);
                    *(float2*)&out[n * FDIM + cb + 8] = make_float2(dp1[0] * sc, dp1[1] * sc);
                }
            }
        }
        __syncthreads();   // pool reads done before prefetch overwrites

        // ---- prefetch tile t+2 into this buffer ----
        prefetch_tile(ebase, mbar, ((long long)tile + 2 * GRID_BLOCKS) * ROWS_PER_TILE,
                      total_rows, tid, is64, nb32, nb64);
    }
}

extern "C" void kernel_launch(void* const* d_in, const int* in_sizes, int n_in,
                              void* d_out, int out_size) {
    const void*  neighbors = d_in[0];
    const float* emb_table = (const float*)d_in[1];
    const float* W         = (const float*)d_in[2];
    const float* b         = (const float*)d_in[3];
    float*       out       = (float*)d_out;

    const int n_nodes = in_sizes[0] / S_SAMPLES;

    cudaFuncSetAttribute(meanpool_kernel,
                         cudaFuncAttributeMaxDynamicSharedMemorySize, SMEM_TOTAL);

    convert_table<<<(TABLE_SIZE * 16 + 255) / 256, 256>>>((const float4*)emb_table,
                                                          (const int*)neighbors);
    meanpool_kernel<<<GRID_BLOCKS, BLOCK_THREADS, SMEM_TOTAL>>>(
        neighbors, W, b, out, n_nodes);
}

// round 15
// speedup vs baseline: 11.7291x; 1.0004x over previous
#include <cuda_runtime.h>
#include <cuda_fp16.h>
#include <cstdint>

// out[n,f] = (1/25) * sum_s relu( dot(E[nbr[n,s],:], W[f,:]) + b[f] )
// f16 HMMA (fp32 accum); table pre-converted to a __device__ f16 mirror.
// Gather: ONE cp.async.bulk (256B) per embedding row into a 272B-stride
// E tile, completion via mbarrier expect_tx. M=128 tiles (5 nodes),
// 256 thr = 8 warps (2m x 4n), 2 CTAs/SM. H (f16) aliases consumed E and is
// written with stmatrix.x4; mean-pool = MMA against block-ones P.
// R15: ks=0 MMA uses c=0 (no acc zero-init), per-warp_m-group named barrier
// after the MMA phase, prefetch indices hoisted to the loop top.

#define S_SAMPLES 25
#define FDIM 128
#define TABLE_SIZE 100000
#define ROWS_PER_TILE 125
#define NODES_PER_TILE 5
#define M_PAD 128
#define BLOCK_THREADS 256
#define GRID_BLOCKS 296            // 2 per SM

#define ROW_STRIDE 272             // 256B data + 16B pad -> conflict-free ldmatrix
#define TILE_BYTES (M_PAD * ROW_STRIDE)   // 34816

#define E0_OFF 0
#define E1_OFF TILE_BYTES          // 34816
#define W_OFF  (2 * TILE_BYTES)    // 69632
#define B_OFF  (3 * TILE_BYTES)    // 104448 (bias 512B)
#define P_OFF  (B_OFF + 512)       // 104960 (pool A-frags 4KB)
#define MBAR_OFF (P_OFF + 4096)    // 109056 (2 x 8B)
#define SMEM_TOTAL (MBAR_OFF + 32)

__device__ int g_idx_is64;
__device__ uint4 g_tab16[TABLE_SIZE * 16];   // f16 table mirror, 256B rows

__device__ __forceinline__ uint32_t pack_h2(float a, float b) {
    uint32_t r;
    asm("cvt.rn.f16x2.f32 %0, %2, %1;" : "=r"(r) : "f"(a), "f"(b));
    return r;
}

// fp32 table -> f16 mirror; block 0 thread 0 also detects the index dtype.
__global__ void convert_table(const float4* __restrict__ table4,
                              const int* __restrict__ nb32) {
    if (blockIdx.x == 0 && threadIdx.x == 0) {
        int is64 = 1;
        #pragma unroll
        for (int i = 1; i < 64; i += 2) if (nb32[i] != 0) is64 = 0;
        g_idx_is64 = is64;
    }
    int i = blockIdx.x * blockDim.x + threadIdx.x;     // 16B chunk index
    if (i >= TABLE_SIZE * 16) return;
    float4 v0 = __ldg(&table4[2 * i]);
    float4 v1 = __ldg(&table4[2 * i + 1]);
    uint4 w;
    w.x = pack_h2(v0.x, v0.y); w.y = pack_h2(v0.z, v0.w);
    w.z = pack_h2(v1.x, v1.y); w.w = pack_h2(v1.z, v1.w);
    g_tab16[i] = w;
}

// ---------------- helpers ----------------
__device__ __forceinline__ uint32_t smem_u32(const void* p) {
    uint32_t a;
    asm("{ .reg .u64 t; cvta.to.shared.u64 t, %1; cvt.u32.u64 %0, t; }" : "=r"(a) : "l"(p));
    return a;
}
// padded-stride addressing (chunk in 16B units)
__device__ __forceinline__ uint32_t ew(int row, int chunk) {
    return (uint32_t)row * ROW_STRIDE + (uint32_t)chunk * 16u;
}
__device__ __forceinline__ void ldm_x4(uint32_t* a, uint32_t addr) {
    asm volatile("ldmatrix.sync.aligned.m8n8.x4.shared.b16 {%0,%1,%2,%3}, [%4];"
                 : "=r"(a[0]), "=r"(a[1]), "=r"(a[2]), "=r"(a[3]) : "r"(addr));
}
__device__ __forceinline__ void ldm_x4_t(uint32_t* a, uint32_t addr) {
    asm volatile("ldmatrix.sync.aligned.m8n8.x4.trans.shared.b16 {%0,%1,%2,%3}, [%4];"
                 : "=r"(a[0]), "=r"(a[1]), "=r"(a[2]), "=r"(a[3]) : "r"(addr));
}
__device__ __forceinline__ void stm_x4(uint32_t addr, const uint32_t* r) {
    asm volatile("stmatrix.sync.aligned.m8n8.x4.shared.b16 [%0], {%1,%2,%3,%4};"
                 :: "r"(addr), "r"(r[0]), "r"(r[1]), "r"(r[2]), "r"(r[3]) : "memory");
}
// accumulate in place: d += a*b
__device__ __forceinline__ void mma_f16(float* d, const uint32_t* a,
                                        uint32_t b0, uint32_t b1) {
    asm volatile(
        "mma.sync.aligned.m16n8k16.row.col.f32.f16.f16.f32 "
        "{%0,%1,%2,%3}, {%4,%5,%6,%7}, {%8,%9}, {%0,%1,%2,%3};"
        : "+f"(d[0]), "+f"(d[1]), "+f"(d[2]), "+f"(d[3])
        : "r"(a[0]), "r"(a[1]), "r"(a[2]), "r"(a[3]), "r"(b0), "r"(b1));
}
// initialize: d = a*b + 0 (no prior accumulator needed)
__device__ __forceinline__ void mma_f16_zc(float* d, const uint32_t* a,
                                           uint32_t b0, uint32_t b1) {
    asm volatile(
        "mma.sync.aligned.m16n8k16.row.col.f32.f16.f16.f32 "
        "{%0,%1,%2,%3}, {%4,%5,%6,%7}, {%8,%9}, {%10,%10,%10,%10};"
        : "=f"(d[0]), "=f"(d[1]), "=f"(d[2]), "=f"(d[3])
        : "r"(a[0]), "r"(a[1]), "r"(a[2]), "r"(a[3]), "r"(b0), "r"(b1),
          "f"(0.0f));
}
__device__ __forceinline__ void mbar_wait(uint32_t mbar, uint32_t parity) {
    asm volatile(
        "{\n\t.reg .pred P;\n\t"
        "W%=:\n\tmbarrier.try_wait.parity.acquire.cta.shared::cta.b64 P, [%0], %1, 0x989680;\n\t"
        "@P bra D%=;\n\tbra W%=;\n\tD%=:\n\t}"
        :: "r"(mbar), "r"(parity) : "memory");
}

__global__ __launch_bounds__(BLOCK_THREADS, 2) void meanpool_kernel(
    const void* __restrict__ neighbors_raw,
    const float* __restrict__ W,
    const float* __restrict__ b,
    float* __restrict__ out,
    int n_nodes)
{
    extern __shared__ char s[];
    const uint32_t sbase = smem_u32(s);
    float* sB = (float*)(s + B_OFF);

    const int tid  = threadIdx.x;
    const int wid  = tid >> 5;
    const int lane = tid & 31;
    const int warp_m = wid & 1;      // 64-row block
    const int warp_n = wid >> 1;     // 32-col block
    const int is64 = g_idx_is64;

    // ---- mbarriers ----
    if (tid == 0) {
        asm volatile("mbarrier.init.shared.b64 [%0], %1;"
                     :: "r"(sbase + MBAR_OFF), "r"(BLOCK_THREADS) : "memory");
        asm volatile("mbarrier.init.shared.b64 [%0], %1;"
                     :: "r"(sbase + MBAR_OFF + 8), "r"(BLOCK_THREADS) : "memory");
    }

    // ---- Stage W (f16, padded rows) + bias; zero E pad rows 125-127 once ----
    const float4* __restrict__ W4 = (const float4*)W;
    for (int i = tid; i < FDIM * 16; i += BLOCK_THREADS) {
        int f = i >> 4, c = i & 15;
        float4 v0 = __ldg(&W4[f * 32 + 2 * c]);
        float4 v1 = __ldg(&W4[f * 32 + 2 * c + 1]);
        uint4 w;
        w.x = pack_h2(v0.x, v0.y); w.y = pack_h2(v0.z, v0.w);
        w.z = pack_h2(v1.x, v1.y); w.w = pack_h2(v1.z, v1.w);
        *(uint4*)(s + W_OFF + ew(f, c)) = w;
    }
    if (tid < (M_PAD - ROWS_PER_TILE) * 16 * 2) {   // 96 threads, once
        int buf = tid >= (M_PAD - ROWS_PER_TILE) * 16;
        int j = tid - buf * (M_PAD - ROWS_PER_TILE) * 16;
        int r = ROWS_PER_TILE + (j >> 4), c = j & 15;
        *(uint4*)(s + (buf ? E1_OFF : E0_OFF) + ew(r, c)) = make_uint4(0u, 0u, 0u, 0u);
    }
    if (tid < FDIM) sB[tid] = __ldg(&b[tid]);

    // ---- Build pool A-fragments P[16x128] (block-ones), m16n8k16 A layout ----
    {
        int kc = tid >> 5, ln = tid & 31;
        int r = ln >> 2, kb = kc * 16 + (ln & 3) * 2;
        uint4 pf;
        uint32_t* pp = (uint32_t*)&pf;
        #pragma unroll
        for (int j = 0; j < 4; ++j) {
            int row = r + ((j & 1) << 3);
            int k = kb + ((j >> 1) << 3);
            float v0 = (row < NODES_PER_TILE && k >= 25 * row && k < 25 * row + 25) ? 1.f : 0.f;
            float v1 = (row < NODES_PER_TILE && k + 1 >= 25 * row && k + 1 < 25 * row + 25) ? 1.f : 0.f;
            pp[j] = pack_h2(v0, v1);
        }
        *(uint4*)(s + P_OFF + tid * 16) = pf;
    }
    __syncthreads();   // mbarrier init + staging visible

    // per-thread bias registers
    float bb[4][2];
    #pragma unroll
    for (int fn = 0; fn < 4; ++fn) {
        int c0 = warp_n * 32 + fn * 8 + (lane & 3) * 2;
        bb[fn][0] = sB[c0];
        bb[fn][1] = sB[c0 + 1];
    }

    const int* __restrict__       nb32 = (const int*)neighbors_raw;
    const long long* __restrict__ nb64 = (const long long*)neighbors_raw;

    const long long total_rows = (long long)n_nodes * S_SAMPLES;
    const int n_tiles = (int)((total_rows + ROWS_PER_TILE - 1) / ROWS_PER_TILE);

    // index loader for a tile (returns -1 if this thread copies nothing)
    auto load_idx = [&](long long row_base) -> int {
        if (row_base < total_rows && tid < ROWS_PER_TILE) {
            long long gr = row_base + tid;
            long long nb = 0;
            if (gr < total_rows)
                nb = is64 ? __ldg(&nb64[gr]) : (long long)__ldg(&nb32[gr]);
            nb = nb < 0 ? 0 : (nb >= TABLE_SIZE ? TABLE_SIZE - 1 : nb);
            return (int)nb;
        }
        return -1;
    };
    auto issue_copy = [&](uint32_t ebase, uint32_t mbar, int pidx) {
        if (pidx >= 0) {
            asm volatile("mbarrier.arrive.expect_tx.shared.b64 _, [%0], 256;"
                         :: "r"(mbar) : "memory");
            asm volatile(
                "cp.async.bulk.shared::cluster.global.mbarrier::complete_tx::bytes "
                "[%0], [%1], 256, [%2];"
                :: "r"(ebase + (uint32_t)tid * ROW_STRIDE),
                   "l"((const char*)g_tab16 + (long long)pidx * 256), "r"(mbar) : "memory");
        } else {
            asm volatile("mbarrier.arrive.shared.b64 _, [%0];" :: "r"(mbar) : "memory");
        }
    };

    // ---- prologue: prefetch t0 -> E0/mbar0, t1 -> E1/mbar1 ----
    issue_copy(sbase + E0_OFF, sbase + MBAR_OFF,
               load_idx((long long)blockIdx.x * ROWS_PER_TILE));
    issue_copy(sbase + E1_OFF, sbase + MBAR_OFF + 8,
               load_idx(((long long)blockIdx.x + GRID_BLOCKS) * ROWS_PER_TILE));

    // per-lane ldmatrix address components (main MMA)
    const int a_row = (lane & 15);
    const int a_kc  = lane >> 4;
    const int b_n   = (lane & 7);
    const int b_kc  = (lane >> 3) & 1;
    const int b_fs  = lane >> 4;
    // pool ldmatrix components
    const int p_row = ((lane >> 3) & 1) * 8 + (lane & 7);
    const int p_cc  = ((wid * 16) + ((lane >> 4) << 3)) >> 3;
    // stmatrix per-lane base
    const uint32_t stm_lane = (uint32_t)(lane & 7) * ROW_STRIDE +
                              (uint32_t)(lane >> 3) * 16u +
                              (uint32_t)warp_m * 64u * ROW_STRIDE +
                              (uint32_t)warp_n * 64u;

    int par0 = 0, par1 = 0;
    int cur = 0;
    for (int tile = blockIdx.x; tile < n_tiles; tile += GRID_BLOCKS, cur ^= 1) {
        const uint32_t ebase = sbase + (cur ? E1_OFF : E0_OFF);
        const uint32_t mbar  = sbase + MBAR_OFF + (cur ? 8 : 0);

        // hoist next-next tile's gather indices (LDG latency hides under MMA)
        const int pidx = load_idx(((long long)tile + 2 * GRID_BLOCKS) * ROWS_PER_TILE);

        // wait for this buffer's gather
        if (cur) { mbar_wait(mbar, par1); par1 ^= 1; }
        else     { mbar_wait(mbar, par0); par0 ^= 1; }

        // ---- main HMMA: 64x32 per warp; ks=0 initializes via c=0 ----
        float acc[4][4][4];
        {
            uint32_t aF[4][4], bW[8];
            #pragma unroll
            for (int fm = 0; fm < 4; ++fm) {
                int row = warp_m * 64 + fm * 16 + a_row;
                ldm_x4(aF[fm], ebase + ew(row, a_kc));
            }
            #pragma unroll
            for (int fp = 0; fp < 2; ++fp) {
                int n = warp_n * 32 + fp * 16 + b_fs * 8 + b_n;
                ldm_x4(bW + fp * 4, sbase + W_OFF + ew(n, b_kc));
            }
            #pragma unroll
            for (int fm = 0; fm < 4; ++fm)
                #pragma unroll
                for (int fn = 0; fn < 4; ++fn)
                    mma_f16_zc(acc[fm][fn], aF[fm], bW[fn * 2], bW[fn * 2 + 1]);
        }
        #pragma unroll
        for (int ks = 1; ks < 8; ++ks) {
            uint32_t aF[4][4], bW[8];
            #pragma unroll
            for (int fm = 0; fm < 4; ++fm) {
                int row = warp_m * 64 + fm * 16 + a_row;
                ldm_x4(aF[fm], ebase + ew(row, ks * 2 + a_kc));
            }
            #pragma unroll
            for (int fp = 0; fp < 2; ++fp) {
                int n = warp_n * 32 + fp * 16 + b_fs * 8 + b_n;
                ldm_x4(bW + fp * 4, sbase + W_OFF + ew(n, ks * 2 + b_kc));
            }
            #pragma unroll
            for (int fm = 0; fm < 4; ++fm)
                #pragma unroll
                for (int fn = 0; fn < 4; ++fn)
                    mma_f16(acc[fm][fn], aF[fm], bW[fn * 2], bW[fn * 2 + 1]);
        }

        // own-group E reads done: group barrier (rows 64*warp_m..+63 private)
        asm volatile("bar.sync %0, 128;" :: "r"(1 + warp_m) : "memory");

        // ---- bias+relu -> H via stmatrix (f16, aliases E[cur], own rows) ----
        #pragma unroll
        for (int fm = 0; fm < 4; ++fm) {
            uint32_t h0[4], h1[4];
            #pragma unroll
            for (int fn = 0; fn < 4; ++fn) {
                h0[fn] = pack_h2(fmaxf(acc[fm][fn][0] + bb[fn][0], 0.f),
                                 fmaxf(acc[fm][fn][1] + bb[fn][1], 0.f));
                h1[fn] = pack_h2(fmaxf(acc[fm][fn][2] + bb[fn][0], 0.f),
                                 fmaxf(acc[fm][fn][3] + bb[fn][1], 0.f));
            }
            uint32_t a0 = ebase + stm_lane + (uint32_t)(fm * 16) * ROW_STRIDE;
            stm_x4(a0, h0);
            stm_x4(a0 + 8u * ROW_STRIDE, h1);
        }
        __syncthreads();   // full H visible to every warp's pool

        // ---- pool MMA: D[5x16 per warp] = P @ H ----
        {
            float dp0[4] = {0.f, 0.f, 0.f, 0.f}, dp1[4] = {0.f, 0.f, 0.f, 0.f};
            #pragma unroll
            for (int kc = 0; kc < 8; ++kc) {
                uint32_t pf[4], bf[4];
                *(uint4*)pf = *(const uint4*)(s + P_OFF + ((kc << 5) + lane) * 16);
                ldm_x4_t(bf, ebase + ew(kc * 16 + p_row, p_cc));
                mma_f16(dp0, pf, bf[0], bf[1]);
                mma_f16(dp1, pf, bf[2], bf[3]);
            }
            int g = lane >> 2;
            if (g < NODES_PER_TILE) {
                long long n = (long long)tile * NODES_PER_TILE + g;
                if (n < n_nodes) {
                    const float sc = 1.0f / (float)S_SAMPLES;
                    int cb = wid * 16 + (lane & 3) * 2;
                    *(float2*)&out[n * FDIM + cb]     = make_float2(dp0[0] * sc, dp0[1] * sc);
                    *(float2*)&out[n * FDIM + cb + 8] = make_float2(dp1[0] * sc, dp1[1] * sc);
                }
            }
        }
        __syncthreads();   // pool reads done before bulk copies overwrite

        // ---- issue prefetch for tile t+2 (indices already in regs) ----
        issue_copy(ebase, mbar, pidx);
    }
}

extern "C" void kernel_launch(void* const* d_in, const int* in_sizes, int n_in,
                              void* d_out, int out_size) {
    const void*  neighbors = d_in[0];
    const float* emb_table = (const float*)d_in[1];
    const float* W         = (const float*)d_in[2];
    const float* b         = (const float*)d_in[3];
    float*       out       = (float*)d_out;

    const int n_nodes = in_sizes[0] / S_SAMPLES;

    cudaFuncSetAttribute(meanpool_kernel,
                         cudaFuncAttributeMaxDynamicSharedMemorySize, SMEM_TOTAL);

    convert_table<<<(TABLE_SIZE * 16 + 255) / 256, 256>>>((const float4*)emb_table,
                                                          (const int*)neighbors);
    meanpool_kernel<<<GRID_BLOCKS, BLOCK_THREADS, SMEM_TOTAL>>>(
        neighbors, W, b, out, n_nodes);
}

// round 16
// speedup vs baseline: 12.0613x; 1.0283x over previous
#include <cuda_runtime.h>
#include <cuda_fp16.h>
#include <cstdint>

// out[n,f] = (1/25) * sum_s relu( dot(E[nbr[n,s],:], W[f,:]) + b[f] )
// f16 HMMA (fp32 accum); table pre-converted to a __device__ f16 mirror.
// Gather: ONE cp.async.bulk (256B) per embedding row into a 272B-stride
// E tile, completion via mbarrier expect_tx. M=128 tiles (5 nodes),
// 256 thr = 8 warps (2m x 4n), 2 CTAs/SM. H (f16) aliases consumed E and is
// written with stmatrix.x4; mean-pool = MMA against block-(1/25) P.
// R16: per-fm ldm/MMA interleave, all-int32 index math, scale folded into P.

#define S_SAMPLES 25
#define FDIM 128
#define TABLE_SIZE 100000
#define ROWS_PER_TILE 125
#define NODES_PER_TILE 5
#define M_PAD 128
#define BLOCK_THREADS 256
#define GRID_BLOCKS 296            // 2 per SM

#define ROW_STRIDE 272             // 256B data + 16B pad -> conflict-free ldmatrix
#define TILE_BYTES (M_PAD * ROW_STRIDE)   // 34816

#define E0_OFF 0
#define E1_OFF TILE_BYTES          // 34816
#define W_OFF  (2 * TILE_BYTES)    // 69632
#define B_OFF  (3 * TILE_BYTES)    // 104448 (bias 512B)
#define P_OFF  (B_OFF + 512)       // 104960 (pool A-frags 4KB)
#define MBAR_OFF (P_OFF + 4096)    // 109056 (2 x 8B)
#define SMEM_TOTAL (MBAR_OFF + 32)

__device__ int g_idx_is64;
__device__ uint4 g_tab16[TABLE_SIZE * 16];   // f16 table mirror, 256B rows

__device__ __forceinline__ uint32_t pack_h2(float a, float b) {
    uint32_t r;
    asm("cvt.rn.f16x2.f32 %0, %2, %1;" : "=r"(r) : "f"(a), "f"(b));
    return r;
}

// fp32 table -> f16 mirror; block 0 thread 0 also detects the index dtype.
__global__ void convert_table(const float4* __restrict__ table4,
                              const int* __restrict__ nb32) {
    if (blockIdx.x == 0 && threadIdx.x == 0) {
        int is64 = 1;
        #pragma unroll
        for (int i = 1; i < 64; i += 2) if (nb32[i] != 0) is64 = 0;
        g_idx_is64 = is64;
    }
    int i = blockIdx.x * blockDim.x + threadIdx.x;     // 16B chunk index
    if (i >= TABLE_SIZE * 16) return;
    float4 v0 = __ldg(&table4[2 * i]);
    float4 v1 = __ldg(&table4[2 * i + 1]);
    uint4 w;
    w.x = pack_h2(v0.x, v0.y); w.y = pack_h2(v0.z, v0.w);
    w.z = pack_h2(v1.x, v1.y); w.w = pack_h2(v1.z, v1.w);
    g_tab16[i] = w;
}

// ---------------- helpers ----------------
__device__ __forceinline__ uint32_t smem_u32(const void* p) {
    uint32_t a;
    asm("{ .reg .u64 t; cvta.to.shared.u64 t, %1; cvt.u32.u64 %0, t; }" : "=r"(a) : "l"(p));
    return a;
}
__device__ __forceinline__ uint32_t ew(int row, int chunk) {
    return (uint32_t)row * ROW_STRIDE + (uint32_t)chunk * 16u;
}
__device__ __forceinline__ void ldm_x4(uint32_t* a, uint32_t addr) {
    asm volatile("ldmatrix.sync.aligned.m8n8.x4.shared.b16 {%0,%1,%2,%3}, [%4];"
                 : "=r"(a[0]), "=r"(a[1]), "=r"(a[2]), "=r"(a[3]) : "r"(addr));
}
__device__ __forceinline__ void ldm_x4_t(uint32_t* a, uint32_t addr) {
    asm volatile("ldmatrix.sync.aligned.m8n8.x4.trans.shared.b16 {%0,%1,%2,%3}, [%4];"
                 : "=r"(a[0]), "=r"(a[1]), "=r"(a[2]), "=r"(a[3]) : "r"(addr));
}
__device__ __forceinline__ void stm_x4(uint32_t addr, const uint32_t* r) {
    asm volatile("stmatrix.sync.aligned.m8n8.x4.shared.b16 [%0], {%1,%2,%3,%4};"
                 :: "r"(addr), "r"(r[0]), "r"(r[1]), "r"(r[2]), "r"(r[3]) : "memory");
}
__device__ __forceinline__ void mma_f16(float* d, const uint32_t* a,
                                        uint32_t b0, uint32_t b1) {
    asm volatile(
        "mma.sync.aligned.m16n8k16.row.col.f32.f16.f16.f32 "
        "{%0,%1,%2,%3}, {%4,%5,%6,%7}, {%8,%9}, {%0,%1,%2,%3};"
        : "+f"(d[0]), "+f"(d[1]), "+f"(d[2]), "+f"(d[3])
        : "r"(a[0]), "r"(a[1]), "r"(a[2]), "r"(a[3]), "r"(b0), "r"(b1));
}
__device__ __forceinline__ void mma_f16_zc(float* d, const uint32_t* a,
                                           uint32_t b0, uint32_t b1) {
    asm volatile(
        "mma.sync.aligned.m16n8k16.row.col.f32.f16.f16.f32 "
        "{%0,%1,%2,%3}, {%4,%5,%6,%7}, {%8,%9}, {%10,%10,%10,%10};"
        : "=f"(d[0]), "=f"(d[1]), "=f"(d[2]), "=f"(d[3])
        : "r"(a[0]), "r"(a[1]), "r"(a[2]), "r"(a[3]), "r"(b0), "r"(b1),
          "f"(0.0f));
}
__device__ __forceinline__ void mbar_wait(uint32_t mbar, uint32_t parity) {
    asm volatile(
        "{\n\t.reg .pred P;\n\t"
        "W%=:\n\tmbarrier.try_wait.parity.acquire.cta.shared::cta.b64 P, [%0], %1, 0x989680;\n\t"
        "@P bra D%=;\n\tbra W%=;\n\tD%=:\n\t}"
        :: "r"(mbar), "r"(parity) : "memory");
}

__global__ __launch_bounds__(BLOCK_THREADS, 2) void meanpool_kernel(
    const void* __restrict__ neighbors_raw,
    const float* __restrict__ W,
    const float* __restrict__ b,
    float* __restrict__ out,
    int n_nodes)
{
    extern __shared__ char s[];
    const uint32_t sbase = smem_u32(s);
    float* sB = (float*)(s + B_OFF);

    const int tid  = threadIdx.x;
    const int wid  = tid >> 5;
    const int lane = tid & 31;
    const int warp_m = wid & 1;      // 64-row block
    const int warp_n = wid >> 1;     // 32-col block
    const int is64 = g_idx_is64;

    // ---- mbarriers ----
    if (tid == 0) {
        asm volatile("mbarrier.init.shared.b64 [%0], %1;"
                     :: "r"(sbase + MBAR_OFF), "r"(BLOCK_THREADS) : "memory");
        asm volatile("mbarrier.init.shared.b64 [%0], %1;"
                     :: "r"(sbase + MBAR_OFF + 8), "r"(BLOCK_THREADS) : "memory");
    }

    // ---- Stage W (f16, padded rows) + bias; zero E pad rows 125-127 once ----
    const float4* __restrict__ W4 = (const float4*)W;
    for (int i = tid; i < FDIM * 16; i += BLOCK_THREADS) {
        int f = i >> 4, c = i & 15;
        float4 v0 = __ldg(&W4[f * 32 + 2 * c]);
        float4 v1 = __ldg(&W4[f * 32 + 2 * c + 1]);
        uint4 w;
        w.x = pack_h2(v0.x, v0.y); w.y = pack_h2(v0.z, v0.w);
        w.z = pack_h2(v1.x, v1.y); w.w = pack_h2(v1.z, v1.w);
        *(uint4*)(s + W_OFF + ew(f, c)) = w;
    }
    if (tid < (M_PAD - ROWS_PER_TILE) * 16 * 2) {   // 96 threads, once
        int buf = tid >= (M_PAD - ROWS_PER_TILE) * 16;
        int j = tid - buf * (M_PAD - ROWS_PER_TILE) * 16;
        int r = ROWS_PER_TILE + (j >> 4), c = j & 15;
        *(uint4*)(s + (buf ? E1_OFF : E0_OFF) + ew(r, c)) = make_uint4(0u, 0u, 0u, 0u);
    }
    if (tid < FDIM) sB[tid] = __ldg(&b[tid]);

    // ---- Build pool A-frags P (block value 1/25 -> scale folded in) ----
    {
        int kc = tid >> 5, ln = tid & 31;
        int r = ln >> 2, kb = kc * 16 + (ln & 3) * 2;
        const float pv = 1.0f / (float)S_SAMPLES;
        uint4 pf;
        uint32_t* pp = (uint32_t*)&pf;
        #pragma unroll
        for (int j = 0; j < 4; ++j) {
            int row = r + ((j & 1) << 3);
            int k = kb + ((j >> 1) << 3);
            float v0 = (row < NODES_PER_TILE && k >= 25 * row && k < 25 * row + 25) ? pv : 0.f;
            float v1 = (row < NODES_PER_TILE && k + 1 >= 25 * row && k + 1 < 25 * row + 25) ? pv : 0.f;
            pp[j] = pack_h2(v0, v1);
        }
        *(uint4*)(s + P_OFF + tid * 16) = pf;
    }
    __syncthreads();   // mbarrier init + staging visible

    // per-thread bias registers
    float bb[4][2];
    #pragma unroll
    for (int fn = 0; fn < 4; ++fn) {
        int c0 = warp_n * 32 + fn * 8 + (lane & 3) * 2;
        bb[fn][0] = sB[c0];
        bb[fn][1] = sB[c0 + 1];
    }

    const int* __restrict__       nb32 = (const int*)neighbors_raw;
    const long long* __restrict__ nb64 = (const long long*)neighbors_raw;

    const int total_rows = n_nodes * S_SAMPLES;          // <= 1.25M, int-safe
    const int n_tiles = (total_rows + ROWS_PER_TILE - 1) / ROWS_PER_TILE;

    // index loader (int32 path; -1 = this thread copies nothing)
    auto load_idx = [&](int row_base) -> int {
        if (row_base < total_rows && tid < ROWS_PER_TILE) {
            int gr = row_base + tid;
            int nb = 0;
            if (gr < total_rows)
                nb = is64 ? (int)__ldg(&nb64[gr]) : __ldg(&nb32[gr]);
            nb = nb < 0 ? 0 : (nb >= TABLE_SIZE ? TABLE_SIZE - 1 : nb);
            return nb;
        }
        return -1;
    };
    auto issue_copy = [&](uint32_t ebase, uint32_t mbar, int pidx) {
        if (pidx >= 0) {
            asm volatile("mbarrier.arrive.expect_tx.shared.b64 _, [%0], 256;"
                         :: "r"(mbar) : "memory");
            asm volatile(
                "cp.async.bulk.shared::cluster.global.mbarrier::complete_tx::bytes "
                "[%0], [%1], 256, [%2];"
                :: "r"(ebase + (uint32_t)tid * ROW_STRIDE),
                   "l"((const char*)g_tab16 + (long long)pidx * 256), "r"(mbar) : "memory");
        } else {
            asm volatile("mbarrier.arrive.shared.b64 _, [%0];" :: "r"(mbar) : "memory");
        }
    };

    // ---- prologue: prefetch t0 -> E0/mbar0, t1 -> E1/mbar1 ----
    issue_copy(sbase + E0_OFF, sbase + MBAR_OFF,
               load_idx(blockIdx.x * ROWS_PER_TILE));
    issue_copy(sbase + E1_OFF, sbase + MBAR_OFF + 8,
               load_idx((blockIdx.x + GRID_BLOCKS) * ROWS_PER_TILE));

    // per-lane ldmatrix address components
    const int a_row = (lane & 15);
    const int a_kc  = lane >> 4;
    const int b_n   = (lane & 7);
    const int b_kc  = (lane >> 3) & 1;
    const int b_fs  = lane >> 4;
    const int p_row = ((lane >> 3) & 1) * 8 + (lane & 7);
    const int p_cc  = ((wid * 16) + ((lane >> 4) << 3)) >> 3;
    const uint32_t stm_lane = (uint32_t)(lane & 7) * ROW_STRIDE +
                              (uint32_t)(lane >> 3) * 16u +
                              (uint32_t)warp_m * 64u * ROW_STRIDE +
                              (uint32_t)warp_n * 64u;

    int par0 = 0, par1 = 0;
    int cur = 0;
    for (int tile = blockIdx.x; tile < n_tiles; tile += GRID_BLOCKS, cur ^= 1) {
        const uint32_t ebase = sbase + (cur ? E1_OFF : E0_OFF);
        const uint32_t mbar  = sbase + MBAR_OFF + (cur ? 8 : 0);

        // hoist next-next tile's gather indices (LDG latency hides under MMA)
        const int pidx = load_idx((tile + 2 * GRID_BLOCKS) * ROWS_PER_TILE);

        // wait for this buffer's gather
        if (cur) { mbar_wait(mbar, par1); par1 ^= 1; }
        else     { mbar_wait(mbar, par0); par0 ^= 1; }

        // ---- main HMMA: 64x32 per warp; per-fm ldm/MMA interleave ----
        float acc[4][4][4];
        const uint32_t a_base = ebase + ew(warp_m * 64 + a_row, a_kc);
        const uint32_t b_base = sbase + W_OFF + ew(warp_n * 32 + b_fs * 8 + b_n, b_kc);

        {   // ks = 0: initialize accumulators via c=0
            uint32_t bW[8];
            ldm_x4(bW,     b_base);
            ldm_x4(bW + 4, b_base + 16u * ROW_STRIDE);
            #pragma unroll
            for (int fm = 0; fm < 4; ++fm) {
                uint32_t aF[4];
                ldm_x4(aF, a_base + (uint32_t)(fm * 16) * ROW_STRIDE);
                #pragma unroll
                for (int fn = 0; fn < 4; ++fn)
                    mma_f16_zc(acc[fm][fn], aF, bW[fn * 2], bW[fn * 2 + 1]);
            }
        }
        #pragma unroll
        for (int ks = 1; ks < 8; ++ks) {
            uint32_t bW[8];
            ldm_x4(bW,     b_base + (uint32_t)(ks * 32));
            ldm_x4(bW + 4, b_base + 16u * ROW_STRIDE + (uint32_t)(ks * 32));
            #pragma unroll
            for (int fm = 0; fm < 4; ++fm) {
                uint32_t aF[4];
                ldm_x4(aF, a_base + (uint32_t)(fm * 16) * ROW_STRIDE + (uint32_t)(ks * 32));
                #pragma unroll
                for (int fn = 0; fn < 4; ++fn)
                    mma_f16(acc[fm][fn], aF, bW[fn * 2], bW[fn * 2 + 1]);
            }
        }

        // own-group E reads done (rows 64*warp_m..+63 private to group)
        asm volatile("bar.sync %0, 128;" :: "r"(1 + warp_m) : "memory");

        // ---- bias+relu -> H via stmatrix (f16, aliases E[cur]) ----
        #pragma unroll
        for (int fm = 0; fm < 4; ++fm) {
            uint32_t h0[4], h1[4];
            #pragma unroll
            for (int fn = 0; fn < 4; ++fn) {
                h0[fn] = pack_h2(fmaxf(acc[fm][fn][0] + bb[fn][0], 0.f),
                                 fmaxf(acc[fm][fn][1] + bb[fn][1], 0.f));
                h1[fn] = pack_h2(fmaxf(acc[fm][fn][2] + bb[fn][0], 0.f),
                                 fmaxf(acc[fm][fn][3] + bb[fn][1], 0.f));
            }
            uint32_t a0 = ebase + stm_lane + (uint32_t)(fm * 16) * ROW_STRIDE;
            stm_x4(a0, h0);
            stm_x4(a0 + 8u * ROW_STRIDE, h1);
        }
        __syncthreads();   // full H visible to every warp's pool

        // ---- pool MMA: D[5x16 per warp] = P @ H (scale folded into P) ----
        {
            float dp0[4] = {0.f, 0.f, 0.f, 0.f}, dp1[4] = {0.f, 0.f, 0.f, 0.f};
            #pragma unroll
            for (int kc = 0; kc < 8; ++kc) {
                uint32_t pf[4], bf[4];
                *(uint4*)pf = *(const uint4*)(s + P_OFF + ((kc << 5) + lane) * 16);
                ldm_x4_t(bf, ebase + ew(kc * 16 + p_row, p_cc));
                mma_f16(dp0, pf, bf[0], bf[1]);
                mma_f16(dp1, pf, bf[2], bf[3]);
            }
            int g = lane >> 2;
            if (g < NODES_PER_TILE) {
                int n = tile * NODES_PER_TILE + g;
                if (n < n_nodes) {
                    int cb = n * FDIM + wid * 16 + (lane & 3) * 2;
                    *(float2*)&out[cb]     = make_float2(dp0[0], dp0[1]);
                    *(float2*)&out[cb + 8] = make_float2(dp1[0], dp1[1]);
                }
            }
        }
        __syncthreads();   // pool reads done before bulk copies overwrite

        // ---- issue prefetch for tile t+2 (indices already in regs) ----
        issue_copy(ebase, mbar, pidx);
    }
}

extern "C" void kernel_launch(void* const* d_in, const int* in_sizes, int n_in,
                              void* d_out, int out_size) {
    const void*  neighbors = d_in[0];
    const float* emb_table = (const float*)d_in[1];
    const float* W         = (const float*)d_in[2];
    const float* b         = (const float*)d_in[3];
    float*       out       = (float*)d_out;

    const int n_nodes = in_sizes[0] / S_SAMPLES;

    cudaFuncSetAttribute(meanpool_kernel,
                         cudaFuncAttributeMaxDynamicSharedMemorySize, SMEM_TOTAL);

    convert_table<<<(TABLE_SIZE * 16 + 255) / 256, 256>>>((const float4*)emb_table,
                                                          (const int*)neighbors);
    meanpool_kernel<<<GRID_BLOCKS, BLOCK_THREADS, SMEM_TOTAL>>>(
        neighbors, W, b, out, n_nodes);
}